// round 13
// baseline (speedup 1.0000x reference)
#include <cuda_runtime.h>
#include <cuda_fp16.h>
#include <math.h>
#include <stdint.h>

#define Bb 8
#define HH 32
#define WW 32
#define E 256
#define HEADS 8
#define KD 32
#define FFN 1024
#define NQ 64
#define L 1024
#define SCALING 0.17677669529663687f
#define LOG2E 1.4426950408889634f
#define NSPLIT 4

#define EPI_NONE 0
#define EPI_GELU 1
#define EPI_THETA 2

// ---------------- scratch arena (float units) ----------------
#define SZ_TOK ((size_t)Bb * L * E)
#define SZ_QTK ((size_t)Bb * NQ * E)
#define OFF_X1    ((size_t)0)
#define OFF_LEPE  (OFF_X1 + SZ_TOK)
#define OFF_X2    (OFF_LEPE + SZ_TOK)
#define OFF_Q2    (OFF_X2 + SZ_TOK)
#define OFF_HN    (OFF_Q2 + SZ_QTK)
#define OFF_QH    (OFF_HN + SZ_TOK / 2)
#define OFF_KH    (OFF_QH + SZ_TOK / 2)
#define OFF_VH    (OFF_KH + SZ_TOK / 2)
#define OFF_AOH   (OFF_VH + SZ_TOK / 2)
#define OFF_XH    (OFF_AOH + SZ_TOK / 2)
#define OFF_CKH   (OFF_XH + SZ_TOK / 2)
#define OFF_CVH   (OFF_CKH + SZ_TOK / 2)
#define OFF_FF    (OFF_CVH + SZ_TOK / 2)
#define OFF_CQH   (OFF_FF + (size_t)Bb * L * FFN / 2)
#define OFF_CAOH  (OFF_CQH + SZ_QTK / 2)
#define OFF_QLN   (OFF_CAOH + SZ_QTK / 2)
#define OFF_QLN2  (OFF_QLN + SZ_QTK / 2)
#define OFF_QFF   (OFF_QLN2 + SZ_QTK / 2)
#define OFF_WH    (OFF_QFF + (size_t)Bb * NQ * FFN / 2)
#define OFF_PO    (OFF_WH + 524288)
#define OFF_PL    (OFF_PO + (size_t)NSPLIT * SZ_QTK)
#define SCRATCH_TOTAL (OFF_PL + (size_t)NSPLIT * Bb * HEADS * NQ)

__device__ float g_scratch[SCRATCH_TOTAL];

// fp16 weight arena offsets (half units)
#define WH_WQ    0
#define WH_WK    65536
#define WH_WV    131072
#define WH_WO    196608
#define WH_FC1   262144
#define WH_FC2   524288
#define WH_CAIN  786432
#define WH_CAOUT 983040

// ---------------- helpers ----------------
__device__ __forceinline__ void cp16(void* dst, const void* src) {
    uint32_t d = (uint32_t)__cvta_generic_to_shared(dst);
    asm volatile("cp.async.cg.shared.global [%0], [%1], 16;" :: "r"(d), "l"(src));
}
#define CP_COMMIT() asm volatile("cp.async.commit_group;" ::: "memory")
#define CP_WAIT(N)  asm volatile("cp.async.wait_group %0;" :: "n"(N) : "memory")

__device__ __forceinline__ uint32_t saddr(const void* p) {
    return (uint32_t)__cvta_generic_to_shared(p);
}

#define LDSM_X4(r0, r1, r2, r3, a)                                          \
    asm volatile("ldmatrix.sync.aligned.m8n8.x4.shared.b16 {%0,%1,%2,%3}, [%4];" \
        : "=r"(r0), "=r"(r1), "=r"(r2), "=r"(r3) : "r"(a))
#define LDSM_X4T(r0, r1, r2, r3, a)                                         \
    asm volatile("ldmatrix.sync.aligned.m8n8.x4.trans.shared.b16 {%0,%1,%2,%3}, [%4];" \
        : "=r"(r0), "=r"(r1), "=r"(r2), "=r"(r3) : "r"(a))

#define MMA_F16(acc, a0, a1, a2, a3, b0, b1)                                \
    asm volatile(                                                           \
        "mma.sync.aligned.m16n8k16.row.col.f32.f16.f16.f32 "                \
        "{%0,%1,%2,%3}, {%4,%5,%6,%7}, {%8,%9}, {%0,%1,%2,%3};"             \
        : "+f"(acc[0]), "+f"(acc[1]), "+f"(acc[2]), "+f"(acc[3])            \
        : "r"(a0), "r"(a1), "r"(a2), "r"(a3), "r"(b0), "r"(b1))

// warp+block reduction of (sum, sumsq)
__device__ __forceinline__ void blk_reduce2(float v, float q, float* out2,
                                            int tid) {
    __shared__ float ws[8], wq[8];
#pragma unroll
    for (int o = 16; o > 0; o >>= 1) {
        v += __shfl_xor_sync(0xffffffff, v, o);
        q += __shfl_xor_sync(0xffffffff, q, o);
    }
    if ((tid & 31) == 0) { ws[tid >> 5] = v; wq[tid >> 5] = q; }
    __syncthreads();
    if (tid < 32) {
        float a = (tid < 8) ? ws[tid] : 0.f;
        float b = (tid < 8) ? wq[tid] : 0.f;
#pragma unroll
        for (int o = 4; o > 0; o >>= 1) {
            a += __shfl_xor_sync(0xffffffff, a, o);
            b += __shfl_xor_sync(0xffffffff, b, o);
        }
        if (tid == 0) { out2[0] = a; out2[1] = b; }
    }
    __syncthreads();
}

// ---------------- weight fp32 -> fp16 conversion ----------------
__global__ void wconv_kernel(const float* __restrict__ wq, const float* __restrict__ wk,
                             const float* __restrict__ wv, const float* __restrict__ wo,
                             const float* __restrict__ fc1, const float* __restrict__ fc2,
                             const float* __restrict__ cain, const float* __restrict__ caout,
                             __half* __restrict__ Wh) {
    const int sizes[8] = {65536, 65536, 65536, 65536, 262144, 262144, 196608, 65536};
    const int offs[8]  = {WH_WQ, WH_WK, WH_WV, WH_WO, WH_FC1, WH_FC2, WH_CAIN, WH_CAOUT};
    int z = blockIdx.y;
    const float* src = z == 0 ? wq : z == 1 ? wk : z == 2 ? wv : z == 3 ? wo
                     : z == 4 ? fc1 : z == 5 ? fc2 : z == 6 ? cain : caout;
    int n = sizes[z];
    __half* dst = Wh + offs[z];
    for (int i = blockIdx.x * 256 + threadIdx.x; i < n; i += gridDim.x * 256)
        dst[i] = __float2half(src[i]);
}

// ---------------- fp16 GEMM core (3-stage pipeline, 128x64 tile) ---------
#define GS 40
__device__ __forceinline__ void gemm16_core(
        const __half* __restrict__ A, const __half* __restrict__ W,
        const float* __restrict__ bias, const float* __restrict__ res,
        float* __restrict__ C, __half* __restrict__ Ch,
        int M, int N, int K, float alpha, int epi,
        const float* __restrict__ sn, const float* __restrict__ cs,
        __half* As, __half* Bs) {
    int tid = threadIdx.x;
    int w = tid >> 5, lane = tid & 31;
    int wm = (w & 3) * 32, wn = (w >> 2) * 32;
    int m0 = blockIdx.y * 128, n0 = blockIdx.x * 64;
    int lg = lane >> 2, lt = lane & 3;
    int ldrow = lane & 15;
    int ldcol = (lane >> 4) * 8;

    float acc[2][4][4] = {};

    auto loadTile = [&](int s, int k0) {
        __half* Ab = As + s * 128 * GS;
        __half* Bd = Bs + s * 64 * GS;
#pragma unroll
        for (int i = 0; i < 2; i++) {
            int id = tid + 256 * i;
            int row = id >> 2, f = id & 3;
            cp16(&Ab[row * GS + f * 8], &A[(size_t)(m0 + row) * K + k0 + f * 8]);
        }
        {
            int row = tid >> 2, f = tid & 3;
            cp16(&Bd[row * GS + f * 8], &W[(size_t)(n0 + row) * K + k0 + f * 8]);
        }
    };

    int KT = K >> 5;
    loadTile(0, 0);
    CP_COMMIT();
    if (KT > 1) { loadTile(1, 32); CP_COMMIT(); }
    for (int kt = 0; kt < KT; kt++) {
        if (kt + 1 < KT) { CP_WAIT(1); } else { CP_WAIT(0); }
        __syncthreads();
        int s = kt % 3;
        const __half* Ab = As + s * 128 * GS;
        const __half* Bd = Bs + s * 64 * GS;
#pragma unroll
        for (int ks = 0; ks < 2; ks++) {
            uint32_t af[2][4];
#pragma unroll
            for (int mi = 0; mi < 2; mi++)
                LDSM_X4(af[mi][0], af[mi][1], af[mi][2], af[mi][3],
                        saddr(&Ab[(wm + mi * 16 + ldrow) * GS + ks * 16 + ldcol]));
#pragma unroll
            for (int nb = 0; nb < 2; nb++) {
                uint32_t b0, b1, b2, b3;
                LDSM_X4(b0, b1, b2, b3,
                        saddr(&Bd[(wn + nb * 16 + ldrow) * GS + ks * 16 + ldcol]));
#pragma unroll
                for (int mi = 0; mi < 2; mi++) {
                    MMA_F16(acc[mi][nb * 2],     af[mi][0], af[mi][1], af[mi][2], af[mi][3], b0, b2);
                    MMA_F16(acc[mi][nb * 2 + 1], af[mi][0], af[mi][1], af[mi][2], af[mi][3], b1, b3);
                }
            }
        }
        if (kt + 2 < KT) { loadTile((kt + 2) % 3, (kt + 2) << 5); CP_COMMIT(); }
    }

    // epilogue
#pragma unroll
    for (int mi = 0; mi < 2; mi++) {
#pragma unroll
        for (int ni = 0; ni < 4; ni++) {
            int r = m0 + wm + mi * 16 + lg;
            int c = n0 + wn + ni * 8 + lt * 2;
            float b0 = bias[c], b1 = bias[c + 1];
#pragma unroll
            for (int half_ = 0; half_ < 2; half_++) {
                int rr = r + half_ * 8;
                float v0 = (acc[mi][ni][half_ * 2 + 0] + b0) * alpha;
                float v1 = (acc[mi][ni][half_ * 2 + 1] + b1) * alpha;
                if (epi == EPI_GELU) {
                    v0 = 0.5f * v0 * (1.0f + erff(v0 * 0.70710678118654752f));
                    v1 = 0.5f * v1 * (1.0f + erff(v1 * 0.70710678118654752f));
                } else if (epi == EPI_THETA) {
                    int l = rr & (L - 1);
                    int d0 = c & 31;
                    const float* sp = sn + l * KD + d0;
                    const float* cq = cs + l * KD + d0;
                    float s0 = sp[0], s1 = sp[1];
                    float c0 = cq[0], c1 = cq[1];
                    float o0 = v0 * c0 - v1 * s0;
                    float o1 = v1 * c1 + v0 * s1;
                    v0 = o0; v1 = o1;
                }
                if (res) {
                    v0 += res[(size_t)rr * N + c];
                    v1 += res[(size_t)rr * N + c + 1];
                }
                if (C)
                    *(float2*)&C[(size_t)rr * N + c] = make_float2(v0, v1);
                if (Ch)
                    *(__half2*)&Ch[(size_t)rr * N + c] = __floats2half2_rn(v0, v1);
            }
        }
    }
}

__global__ __launch_bounds__(256) void gemm_kernel(
        const __half* __restrict__ A, const __half* __restrict__ W,
        const float* __restrict__ bias, const float* __restrict__ res,
        float* __restrict__ C, __half* __restrict__ Ch,
        int M, int N, int K, float alpha, int epi) {
    __shared__ __align__(16) __half As[3 * 128 * GS];
    __shared__ __align__(16) __half Bs[3 * 64 * GS];
    gemm16_core(A, W, bias, res, C, Ch, M, N, K, alpha, epi, nullptr, nullptr, As, Bs);
}

__global__ __launch_bounds__(256) void qkv_gemm_kernel(
        const __half* __restrict__ HN, const __half* __restrict__ Wh,
        const float* __restrict__ bq, const float* __restrict__ bk,
        const float* __restrict__ bv,
        __half* __restrict__ QH, __half* __restrict__ KH,
        __half* __restrict__ VH,
        const float* __restrict__ sn, const float* __restrict__ cs) {
    __shared__ __align__(16) __half As[3 * 128 * GS];
    __shared__ __align__(16) __half Bs[3 * 64 * GS];
    int z = blockIdx.z;
    const __half* W = Wh + (z == 0 ? WH_WQ : z == 1 ? WH_WK : WH_WV);
    const float* bias = (z == 0) ? bq : (z == 1) ? bk : bv;
    __half* Ch = (z == 0) ? QH : (z == 1) ? KH : VH;
    float alpha = (z == 1) ? SCALING : 1.f;
    int epi = (z == 2) ? EPI_NONE : EPI_THETA;
    gemm16_core(HN, W, bias, nullptr, nullptr, Ch, Bb * L, E, E, alpha, epi, sn, cs, As, Bs);
}

__global__ __launch_bounds__(256) void ckv_gemm_kernel(
        const __half* __restrict__ XH, const __half* __restrict__ Wh,
        const float* __restrict__ ca_in_b,
        __half* __restrict__ CKH, __half* __restrict__ CVH) {
    __shared__ __align__(16) __half As[3 * 128 * GS];
    __shared__ __align__(16) __half Bs[3 * 64 * GS];
    int z = blockIdx.z;
    const __half* W = Wh + WH_CAIN + (size_t)(z + 1) * E * E;
    const float* bias = ca_in_b + (z + 1) * E;
    __half* Ch = z ? CVH : CKH;
    gemm16_core(XH, W, bias, nullptr, nullptr, Ch, Bb * L, E, E, 1.f, EPI_NONE,
                nullptr, nullptr, As, Bs);
}

// ---------------- fused dwconv3x3(+in) + LN1 --------------------------
__global__ void dwconv3_ln_kernel(const float* __restrict__ in,
                                  const float* __restrict__ w,
                                  const float* __restrict__ bias,
                                  const float* __restrict__ g,
                                  const float* __restrict__ bln,
                                  float* __restrict__ X1,
                                  __half* __restrict__ HN) {
    int c = threadIdx.x;
    int wx = blockIdx.x, hy = blockIdx.y, b = blockIdx.z;
    float acc = bias[c];
#pragma unroll
    for (int kh = 0; kh < 3; kh++) {
        int y = hy + kh - 1;
        if (y < 0 || y >= HH) continue;
#pragma unroll
        for (int kw = 0; kw < 3; kw++) {
            int xx = wx + kw - 1;
            if (xx < 0 || xx >= WW) continue;
            acc += in[(((size_t)b * HH + y) * WW + xx) * E + c] *
                   w[c * 9 + kh * 3 + kw];
        }
    }
    size_t o = (((size_t)b * HH + hy) * WW + wx) * E + c;
    float v = in[o] + acc;
    X1[o] = v;
    __shared__ float red[2];
    blk_reduce2(v, v * v, red, c);
    float m = red[0] * (1.0f / E);
    float var = red[1] * (1.0f / E) - m * m;
    float inv = rsqrtf(var + 1e-6f);
    HN[o] = __float2half((v - m) * inv * g[c] + bln[c]);
}

// ---------------- dwconv 5x5: fp16 in, fp32 out, 4 px/thread (R7 form) ---
__global__ __launch_bounds__(256) void dwconv5_kernel(
        const __half* __restrict__ VH, const float* __restrict__ w,
        const float* __restrict__ bias, float* __restrict__ out) {
    int c = threadIdx.x;
    int x0 = blockIdx.x * 4, hy = blockIdx.y, b = blockIdx.z;
    float wreg[25];
#pragma unroll
    for (int i = 0; i < 25; i++) wreg[i] = w[c * 25 + i];
    float bz = bias[c];
    float acc[4] = {bz, bz, bz, bz};
#pragma unroll
    for (int kh = 0; kh < 5; kh++) {
        int y = hy + kh - 2;
        if (y < 0 || y >= HH) continue;
        const __half* rbase = VH + (((size_t)b * HH + y) * WW) * E + c;
#pragma unroll
        for (int kw = 0; kw < 8; kw++) {
            int xx = x0 + kw - 2;
            if (xx < 0 || xx >= WW) continue;
            float v = __half2float(rbase[(size_t)xx * E]);
            int dx = kw - 2;
#pragma unroll
            for (int j = 0; j < 4; j++) {
                int kwi = dx - j + 2;
                if (kwi >= 0 && kwi < 5)
                    acc[j] += v * wreg[kh * 5 + kwi];
            }
        }
    }
    size_t obase = (((size_t)b * HH + hy) * WW + x0) * E + c;
#pragma unroll
    for (int j = 0; j < 4; j++)
        out[obase + (size_t)j * E] = acc[j];
}

// ---------------- layernorm (fp32 in, fp16 out) ------------------------
__global__ void ln_kernel(const float* __restrict__ in,
                          const float* __restrict__ g,
                          const float* __restrict__ b,
                          __half* __restrict__ out) {
    int row = blockIdx.x;
    int t = threadIdx.x;
    float v = in[(size_t)row * E + t];
    __shared__ float red[2];
    blk_reduce2(v, v * v, red, t);
    float m = red[0] * (1.0f / E);
    float var = red[1] * (1.0f / E) - m * m;
    float inv = rsqrtf(var + 1e-6f);
    out[(size_t)row * E + t] = __float2half((v - m) * inv * g[t] + b[t]);
}

// ---------------- fp16 flash attention, fixed-max softmax ----------------
// Template QT = queries per block (16 per warp). Mask preloaded before
// S-mma so LDG overlaps tensor ops. nsplit>1: unnormalized partials.
// dyn smem layout (halves): Qs[QT*40] | Ks[3][64*40] | Vs[3][64*40] | Ps[QT*72]
#define KVS 40
#define PSS 72
template <int QT>
__global__ __launch_bounds__(QT * 2) void attn_f16_kernel(
        const __half* __restrict__ Q, const __half* __restrict__ Kt,
        const __half* __restrict__ V,
        const float* __restrict__ mask, const float* __restrict__ addend,
        __half* __restrict__ O, float* __restrict__ PO, float* __restrict__ PL,
        int Lq, int Lk, float scale, int nsplit) {
    extern __shared__ __half sm[];
    __half* Qs = sm;
    __half* KsB = sm + QT * KVS;
    __half* VsB = KsB + 3 * 64 * KVS;
    __half* Ps = VsB + 3 * 64 * KVS;
    const int NTH = QT * 2;

    int tid = threadIdx.x;
    int w = tid >> 5, lane = tid & 31;
    int lg = lane >> 2, lt = lane & 3;
    int h = blockIdx.y, b = blockIdx.z;
    int qtiles = Lq / QT;
    int split = blockIdx.x / qtiles;
    int q0 = (blockIdx.x - split * qtiles) * QT;
    int wm = w * 16;
    int ldrow = lane & 15;
    int ldcol = (lane >> 4) * 8;

    int NJ = (Lk >> 6) / nsplit;
    int jbase = split * NJ;

    auto loadQ = [&]() {
        const __half* src = Q + ((size_t)(b * Lq + q0)) * E + h * KD;
#pragma unroll
        for (int id = tid; id < QT * 4; id += NTH) {
            int row = id >> 2, gr = id & 3;
            cp16(Qs + row * KVS + gr * 8, src + (size_t)row * E + gr * 8);
        }
    };
    auto loadKV = [&](int s, int chunk) {
        const __half* ksrc = Kt + ((size_t)(b * Lk + (chunk << 6))) * E + h * KD;
        const __half* vsrc = V  + ((size_t)(b * Lk + (chunk << 6))) * E + h * KD;
        __half* Kd = KsB + s * 64 * KVS;
        __half* Vd = VsB + s * 64 * KVS;
#pragma unroll
        for (int id = tid; id < 256; id += NTH) {
            int row = id >> 2, gr = id & 3;
            cp16(Kd + row * KVS + gr * 8, ksrc + (size_t)row * E + gr * 8);
            cp16(Vd + row * KVS + gr * 8, vsrc + (size_t)row * E + gr * 8);
        }
        CP_COMMIT();
    };

    loadQ();
    CP_COMMIT();
    loadKV(0, jbase);
    if (NJ > 1) loadKV(1, jbase + 1);
    CP_WAIT(2);
    __syncthreads();

    uint32_t qf[2][4];
#pragma unroll
    for (int ks = 0; ks < 2; ks++)
        LDSM_X4(qf[ks][0], qf[ks][1], qf[ks][2], qf[ks][3],
                saddr(&Qs[(wm + ldrow) * KVS + ks * 16 + ldcol]));

    float ps0 = 0.f, ps1 = 0.f;
    float oacc[4][4] = {};
    const float* mbase = mask ? (mask + ((size_t)h * Lk + q0) * Lk) : nullptr;
    float sl2 = scale * LOG2E;

    for (int jt = 0; jt < NJ; jt++) {
        int j0 = (jbase + jt) << 6;
        if (jt + 1 < NJ) { CP_WAIT(1); } else { CP_WAIT(0); }
        __syncthreads();
        int s = jt % 3;
        const __half* Ks = KsB + s * 64 * KVS;
        const __half* Vs = VsB + s * 64 * KVS;

        // preload mask BEFORE the S-mma (LDG hides under tensor ops)
        float2 mv[8][2];
        if (mbase) {
            int r0 = wm + lg, r1 = wm + 8 + lg;
#pragma unroll
            for (int ni = 0; ni < 8; ni++) {
                int c = j0 + ni * 8 + lt * 2;
                mv[ni][0] = *(const float2*)&mbase[(size_t)r0 * Lk + c];
                mv[ni][1] = *(const float2*)&mbase[(size_t)r1 * Lk + c];
            }
        }

        float sacc[8][4];
#pragma unroll
        for (int ni = 0; ni < 8; ni++)
#pragma unroll
            for (int c = 0; c < 4; c++) sacc[ni][c] = 0.f;
#pragma unroll
        for (int ks = 0; ks < 2; ks++) {
#pragma unroll
            for (int nb = 0; nb < 4; nb++) {
                uint32_t r0, r1, r2, r3;
                LDSM_X4(r0, r1, r2, r3,
                        saddr(&Ks[(nb * 16 + ldrow) * KVS + ks * 16 + ldcol]));
                MMA_F16(sacc[2 * nb],     qf[ks][0], qf[ks][1], qf[ks][2], qf[ks][3], r0, r2);
                MMA_F16(sacc[2 * nb + 1], qf[ks][0], qf[ks][1], qf[ks][2], qf[ks][3], r1, r3);
            }
        }

        // exp (fixed max = 0) + P store + running row sums
#pragma unroll
        for (int ni = 0; ni < 8; ni++) {
            float p0, p1, p2, p3;
            if (mbase) {
                p0 = exp2f((sacc[ni][0] + mv[ni][0].x) * LOG2E);
                p1 = exp2f((sacc[ni][1] + mv[ni][0].y) * LOG2E);
                p2 = exp2f((sacc[ni][2] + mv[ni][1].x) * LOG2E);
                p3 = exp2f((sacc[ni][3] + mv[ni][1].y) * LOG2E);
            } else {
                p0 = exp2f(sacc[ni][0] * sl2);
                p1 = exp2f(sacc[ni][1] * sl2);
                p2 = exp2f(sacc[ni][2] * sl2);
                p3 = exp2f(sacc[ni][3] * sl2);
            }
            ps0 += p0 + p1;
            ps1 += p2 + p3;
            int c = ni * 8 + lt * 2;
            *(__half2*)&Ps[(wm + lg) * PSS + c]     = __floats2half2_rn(p0, p1);
            *(__half2*)&Ps[(wm + 8 + lg) * PSS + c] = __floats2half2_rn(p2, p3);
        }
        __syncwarp();

#pragma unroll
        for (int ks = 0; ks < 4; ks++) {
            uint32_t pa0, pa1, pa2, pa3;
            LDSM_X4(pa0, pa1, pa2, pa3,
                    saddr(&Ps[(wm + ldrow) * PSS + ks * 16 + ldcol]));
            uint32_t v0, v1, v2, v3;
            LDSM_X4T(v0, v1, v2, v3,
                     saddr(&Vs[(ks * 16 + ldrow) * KVS + 0 + ldcol]));
            uint32_t u0, u1, u2, u3;
            LDSM_X4T(u0, u1, u2, u3,
                     saddr(&Vs[(ks * 16 + ldrow) * KVS + 16 + ldcol]));
            MMA_F16(oacc[0], pa0, pa1, pa2, pa3, v0, v1);
            MMA_F16(oacc[1], pa0, pa1, pa2, pa3, v2, v3);
            MMA_F16(oacc[2], pa0, pa1, pa2, pa3, u0, u1);
            MMA_F16(oacc[3], pa0, pa1, pa2, pa3, u2, u3);
        }
        if (jt + 2 < NJ) loadKV((jt + 2) % 3, jbase + jt + 2);
    }

    // row-sum reduce across the quad
    ps0 += __shfl_xor_sync(0xffffffff, ps0, 1);
    ps0 += __shfl_xor_sync(0xffffffff, ps0, 2);
    ps1 += __shfl_xor_sync(0xffffffff, ps1, 1);
    ps1 += __shfl_xor_sync(0xffffffff, ps1, 2);

    int r0 = q0 + wm + lg, r1 = r0 + 8;
    if (nsplit == 1) {
        float inv0 = 1.f / ps0, inv1 = 1.f / ps1;
#pragma unroll
        for (int ni = 0; ni < 4; ni++) {
            int c = h * KD + ni * 8 + lt * 2;
            float v00 = oacc[ni][0] * inv0, v01 = oacc[ni][1] * inv0;
            float v10 = oacc[ni][2] * inv1, v11 = oacc[ni][3] * inv1;
            if (addend) {
                float2 a0 = *(const float2*)&addend[((size_t)(b * Lq + r0)) * E + c];
                float2 a1 = *(const float2*)&addend[((size_t)(b * Lq + r1)) * E + c];
                v00 += a0.x; v01 += a0.y; v10 += a1.x; v11 += a1.y;
            }
            *(__half2*)&O[((size_t)(b * Lq + r0)) * E + c] = __floats2half2_rn(v00, v01);
            *(__half2*)&O[((size_t)(b * Lq + r1)) * E + c] = __floats2half2_rn(v10, v11);
        }
    } else {
        size_t base = (size_t)split * Bb * Lq;
#pragma unroll
        for (int ni = 0; ni < 4; ni++) {
            int c = h * KD + ni * 8 + lt * 2;
            *(float2*)&PO[(base + b * Lq + r0) * E + c] =
                make_float2(oacc[ni][0], oacc[ni][1]);
            *(float2*)&PO[(base + b * Lq + r1) * E + c] =
                make_float2(oacc[ni][2], oacc[ni][3]);
        }
        if (lt == 0) {
            size_t plb = (((size_t)split * Bb + b) * HEADS + h) * Lq;
            PL[plb + r0] = ps0;
            PL[plb + r1] = ps1;
        }
    }
}

#define ATTN_SMEM(QT) ((QT * KVS + 6 * 64 * KVS + QT * PSS) * 2)

// ---------------- split-KV reduce: out = Σpo / Σl ------------------------
__global__ void attn_reduce_kernel(const float* __restrict__ PO,
                                   const float* __restrict__ PL,
                                   __half* __restrict__ out) {
    int idx = blockIdx.x * 256 + threadIdx.x;      // over Bb*NQ*E
    int e = idx & (E - 1);
    int bq = idx >> 8;
    int q = bq & (NQ - 1);
    int b = bq >> 6;
    int h = e >> 5;
    float num = 0.f, den = 0.f;
#pragma unroll
    for (int s = 0; s < NSPLIT; s++) {
        num += PO[((size_t)s * Bb * NQ + bq) * E + e];
        den += PL[(((size_t)s * Bb + b) * HEADS + h) * NQ + q];
    }
    out[idx] = __float2half(num / den);
}

// ---------------- launcher ----------------------------------------------
extern "C" void kernel_launch(void* const* d_in, const int* in_sizes, int n_in,
                              void* d_out, int out_size) {
    const float* x       = (const float*)d_in[0];
    const float* queries = (const float*)d_in[1];
    const float* sn      = (const float*)d_in[2];
    const float* cs      = (const float*)d_in[3];
    const float* mask    = (const float*)d_in[4];
    const float* ln1_g   = (const float*)d_in[5];
    const float* ln1_b   = (const float*)d_in[6];
    const float* ln2_g   = (const float*)d_in[7];
    const float* ln2_b   = (const float*)d_in[8];
    const float* wq      = (const float*)d_in[9];
    const float* bq      = (const float*)d_in[10];
    const float* wk      = (const float*)d_in[11];
    const float* bk      = (const float*)d_in[12];
    const float* wv      = (const float*)d_in[13];
    const float* bv      = (const float*)d_in[14];
    const float* lepe_w  = (const float*)d_in[15];
    const float* lepe_b  = (const float*)d_in[16];
    const float* wo      = (const float*)d_in[17];
    const float* bo      = (const float*)d_in[18];
    const float* fc1_w   = (const float*)d_in[19];
    const float* fc1_b   = (const float*)d_in[20];
    const float* fc2_w   = (const float*)d_in[21];
    const float* fc2_b   = (const float*)d_in[22];
    const float* pos_w   = (const float*)d_in[23];
    const float* pos_b   = (const float*)d_in[24];
    const float* ca_in_w = (const float*)d_in[25];
    const float* ca_in_b = (const float*)d_in[26];
    const float* ca_out_w= (const float*)d_in[27];
    const float* ca_out_b= (const float*)d_in[28];

    void* sp = nullptr;
    cudaGetSymbolAddress(&sp, g_scratch);
    float* S = (float*)sp;
    float* X1   = S + OFF_X1;
    float* LEPE = S + OFF_LEPE;
    float* X2   = S + OFF_X2;
    float* Q2   = S + OFF_Q2;
    float* PO   = S + OFF_PO;
    float* PL   = S + OFF_PL;
    __half* HN   = (__half*)(S + OFF_HN);
    __half* QH   = (__half*)(S + OFF_QH);
    __half* KH   = (__half*)(S + OFF_KH);
    __half* VH   = (__half*)(S + OFF_VH);
    __half* AOH  = (__half*)(S + OFF_AOH);
    __half* XH   = (__half*)(S + OFF_XH);
    __half* CKH  = (__half*)(S + OFF_CKH);
    __half* CVH  = (__half*)(S + OFF_CVH);
    __half* FF   = (__half*)(S + OFF_FF);
    __half* CQH  = (__half*)(S + OFF_CQH);
    __half* CAOH = (__half*)(S + OFF_CAOH);
    __half* QLN  = (__half*)(S + OFF_QLN);
    __half* QLN2 = (__half*)(S + OFF_QLN2);
    __half* QFF  = (__half*)(S + OFF_QFF);
    __half* WHb  = (__half*)(S + OFF_WH);

    float* OX = (float*)d_out;
    float* OQ = OX + (size_t)Bb * L * E;

    const int MTOK = Bb * L;   // 8192
    const int MQ   = Bb * NQ;  // 512
    dim3 sp3(WW, HH, Bb);
    dim3 c5(WW / 4, HH, Bb);

    static bool attr_set = false;
    if (!attr_set) {
        cudaFuncSetAttribute(attn_f16_kernel<128>,
            cudaFuncAttributeMaxDynamicSharedMemorySize, ATTN_SMEM(128));
        cudaFuncSetAttribute(attn_f16_kernel<64>,
            cudaFuncAttributeMaxDynamicSharedMemorySize, ATTN_SMEM(64));
        attr_set = true;
    }

    // 0. weights -> fp16
    wconv_kernel<<<dim3(128, 8), 256>>>(wq, wk, wv, wo, fc1_w, fc2_w,
                                        ca_in_w, ca_out_w, WHb);
    // 1. x1 = x + dwconv3(x); hn = LN1(x1) fp16
    dwconv3_ln_kernel<<<sp3, 256>>>(x, pos_w, pos_b, ln1_g, ln1_b, X1, HN);
    // 2. q(theta), k(theta,*scaling), v(fp16)
    qkv_gemm_kernel<<<dim3(E/64, MTOK/128, 3), 256>>>(
        HN, WHb, bq, bk, bv, QH, KH, VH, sn, cs);
    // 3. lepe = dwconv5(v)
    dwconv5_kernel<<<c5, 256>>>(VH, lepe_w, lepe_b, LEPE);
    // 4. self attention (128-query tile) + lepe -> AOH fp16
    attn_f16_kernel<128><<<dim3(L/128, HEADS, Bb), 256, ATTN_SMEM(128)>>>(
        QH, KH, VH, mask, LEPE, AOH, nullptr, nullptr, L, L, 1.f, 1);
    // 5. x2 = x1 + aoh @ wo^T + bo
    gemm_kernel<<<dim3(E/64, MTOK/128), 256>>>(AOH, WHb + WH_WO, bo, X1, X2, nullptr, MTOK, E, E, 1.f, EPI_NONE);
    // 6. FFN on x
    ln_kernel<<<MTOK, 256>>>(X2, ln2_g, ln2_b, HN);
    gemm_kernel<<<dim3(FFN/64, MTOK/128), 256>>>(HN, WHb + WH_FC1, fc1_b, nullptr, nullptr, FF, MTOK, FFN, E, 1.f, EPI_GELU);
    gemm_kernel<<<dim3(E/64, MTOK/128), 256>>>(FF, WHb + WH_FC2, fc2_b, X2, OX, XH, MTOK, E, FFN, 1.f, EPI_NONE);
    // 7. cross attention (split-KV, 64-query tile)
    ln_kernel<<<MQ, 256>>>(queries, ln1_g, ln1_b, QLN);
    gemm_kernel<<<dim3(E/64, MQ/128), 256>>>(QLN, WHb + WH_CAIN, ca_in_b, nullptr, nullptr, CQH, MQ, E, E, 1.f, EPI_NONE);
    ckv_gemm_kernel<<<dim3(E/64, MTOK/128, 2), 256>>>(XH, WHb, ca_in_b, CKH, CVH);
    attn_f16_kernel<64><<<dim3(NSPLIT, HEADS, Bb), 128, ATTN_SMEM(64)>>>(
        CQH, CKH, CVH, nullptr, nullptr, nullptr, PO, PL, NQ, L, SCALING, NSPLIT);
    attn_reduce_kernel<<<(Bb * NQ * E) / 256, 256>>>(PO, PL, CAOH);
    gemm_kernel<<<dim3(E/64, MQ/128), 256>>>(CAOH, WHb + WH_CAOUT, ca_out_b, queries, Q2, nullptr, MQ, E, E, 1.f, EPI_NONE);
    // 8. FFN on queries
    ln_kernel<<<MQ, 256>>>(Q2, ln2_g, ln2_b, QLN2);
    gemm_kernel<<<dim3(FFN/64, MQ/128), 256>>>(QLN2, WHb + WH_FC1, fc1_b, nullptr, nullptr, QFF, MQ, FFN, E, 1.f, EPI_GELU);
    gemm_kernel<<<dim3(E/64, MQ/128), 256>>>(QFF, WHb + WH_FC2, fc2_b, Q2, OQ, nullptr, MQ, E, FFN, 1.f, EPI_NONE);
}

// round 14
// speedup vs baseline: 1.0316x; 1.0316x over previous
#include <cuda_runtime.h>
#include <cuda_fp16.h>
#include <math.h>
#include <stdint.h>

#define Bb 8
#define HH 32
#define WW 32
#define E 256
#define HEADS 8
#define KD 32
#define FFN 1024
#define NQ 64
#define L 1024
#define SCALING 0.17677669529663687f
#define LOG2E 1.4426950408889634f
#define NSPLIT 4

#define EPI_NONE 0
#define EPI_GELU 1
#define EPI_THETA 2

// ---------------- scratch arena (float units) ----------------
#define SZ_TOK ((size_t)Bb * L * E)
#define SZ_QTK ((size_t)Bb * NQ * E)
#define OFF_X1    ((size_t)0)
#define OFF_LEPE  (OFF_X1 + SZ_TOK)
#define OFF_X2    (OFF_LEPE + SZ_TOK)
#define OFF_Q2    (OFF_X2 + SZ_TOK)
#define OFF_HN    (OFF_Q2 + SZ_QTK)
#define OFF_QH    (OFF_HN + SZ_TOK / 2)
#define OFF_KH    (OFF_QH + SZ_TOK / 2)
#define OFF_VH    (OFF_KH + SZ_TOK / 2)
#define OFF_AOH   (OFF_VH + SZ_TOK / 2)
#define OFF_XH    (OFF_AOH + SZ_TOK / 2)
#define OFF_CKH   (OFF_XH + SZ_TOK / 2)
#define OFF_CVH   (OFF_CKH + SZ_TOK / 2)
#define OFF_FF    (OFF_CVH + SZ_TOK / 2)
#define OFF_CQH   (OFF_FF + (size_t)Bb * L * FFN / 2)
#define OFF_CAOH  (OFF_CQH + SZ_QTK / 2)
#define OFF_QLN   (OFF_CAOH + SZ_QTK / 2)
#define OFF_QLN2  (OFF_QLN + SZ_QTK / 2)
#define OFF_QFF   (OFF_QLN2 + SZ_QTK / 2)
#define OFF_WH    (OFF_QFF + (size_t)Bb * NQ * FFN / 2)
#define OFF_PO    (OFF_WH + 524288)
#define OFF_PL    (OFF_PO + (size_t)NSPLIT * SZ_QTK)
#define SCRATCH_TOTAL (OFF_PL + (size_t)NSPLIT * Bb * HEADS * NQ)

__device__ float g_scratch[SCRATCH_TOTAL];

// fp16 weight arena offsets (half units)
#define WH_WQ    0
#define WH_WK    65536
#define WH_WV    131072
#define WH_WO    196608
#define WH_FC1   262144
#define WH_FC2   524288
#define WH_CAIN  786432
#define WH_CAOUT 983040

// ---------------- helpers ----------------
__device__ __forceinline__ void cp16(void* dst, const void* src) {
    uint32_t d = (uint32_t)__cvta_generic_to_shared(dst);
    asm volatile("cp.async.cg.shared.global [%0], [%1], 16;" :: "r"(d), "l"(src));
}
#define CP_COMMIT() asm volatile("cp.async.commit_group;" ::: "memory")
#define CP_WAIT(N)  asm volatile("cp.async.wait_group %0;" :: "n"(N) : "memory")

__device__ __forceinline__ uint32_t saddr(const void* p) {
    return (uint32_t)__cvta_generic_to_shared(p);
}

#define LDSM_X4(r0, r1, r2, r3, a)                                          \
    asm volatile("ldmatrix.sync.aligned.m8n8.x4.shared.b16 {%0,%1,%2,%3}, [%4];" \
        : "=r"(r0), "=r"(r1), "=r"(r2), "=r"(r3) : "r"(a))
#define LDSM_X4T(r0, r1, r2, r3, a)                                         \
    asm volatile("ldmatrix.sync.aligned.m8n8.x4.trans.shared.b16 {%0,%1,%2,%3}, [%4];" \
        : "=r"(r0), "=r"(r1), "=r"(r2), "=r"(r3) : "r"(a))

#define MMA_F16(acc, a0, a1, a2, a3, b0, b1)                                \
    asm volatile(                                                           \
        "mma.sync.aligned.m16n8k16.row.col.f32.f16.f16.f32 "                \
        "{%0,%1,%2,%3}, {%4,%5,%6,%7}, {%8,%9}, {%0,%1,%2,%3};"             \
        : "+f"(acc[0]), "+f"(acc[1]), "+f"(acc[2]), "+f"(acc[3])            \
        : "r"(a0), "r"(a1), "r"(a2), "r"(a3), "r"(b0), "r"(b1))

// warp+block reduction of (sum, sumsq)
__device__ __forceinline__ void blk_reduce2(float v, float q, float* out2,
                                            int tid) {
    __shared__ float ws[8], wq[8];
#pragma unroll
    for (int o = 16; o > 0; o >>= 1) {
        v += __shfl_xor_sync(0xffffffff, v, o);
        q += __shfl_xor_sync(0xffffffff, q, o);
    }
    if ((tid & 31) == 0) { ws[tid >> 5] = v; wq[tid >> 5] = q; }
    __syncthreads();
    if (tid < 32) {
        float a = (tid < 8) ? ws[tid] : 0.f;
        float b = (tid < 8) ? wq[tid] : 0.f;
#pragma unroll
        for (int o = 4; o > 0; o >>= 1) {
            a += __shfl_xor_sync(0xffffffff, a, o);
            b += __shfl_xor_sync(0xffffffff, b, o);
        }
        if (tid == 0) { out2[0] = a; out2[1] = b; }
    }
    __syncthreads();
}

// ---------------- weight fp32 -> fp16 conversion ----------------
__global__ void wconv_kernel(const float* __restrict__ wq, const float* __restrict__ wk,
                             const float* __restrict__ wv, const float* __restrict__ wo,
                             const float* __restrict__ fc1, const float* __restrict__ fc2,
                             const float* __restrict__ cain, const float* __restrict__ caout,
                             __half* __restrict__ Wh) {
    const int sizes[8] = {65536, 65536, 65536, 65536, 262144, 262144, 196608, 65536};
    const int offs[8]  = {WH_WQ, WH_WK, WH_WV, WH_WO, WH_FC1, WH_FC2, WH_CAIN, WH_CAOUT};
    int z = blockIdx.y;
    const float* src = z == 0 ? wq : z == 1 ? wk : z == 2 ? wv : z == 3 ? wo
                     : z == 4 ? fc1 : z == 5 ? fc2 : z == 6 ? cain : caout;
    int n = sizes[z];
    __half* dst = Wh + offs[z];
    for (int i = blockIdx.x * 256 + threadIdx.x; i < n; i += gridDim.x * 256)
        dst[i] = __float2half(src[i]);
}

// ---------------- fp16 GEMM core (3-stage pipeline, 128x64 tile) ---------
#define GS 40
__device__ __forceinline__ void gemm16_core(
        const __half* __restrict__ A, const __half* __restrict__ W,
        const float* __restrict__ bias, const float* __restrict__ res,
        float* __restrict__ C, __half* __restrict__ Ch,
        int M, int N, int K, float alpha, int epi,
        const float* __restrict__ sn, const float* __restrict__ cs,
        __half* As, __half* Bs) {
    int tid = threadIdx.x;
    int w = tid >> 5, lane = tid & 31;
    int wm = (w & 3) * 32, wn = (w >> 2) * 32;
    int m0 = blockIdx.y * 128, n0 = blockIdx.x * 64;
    int lg = lane >> 2, lt = lane & 3;
    int ldrow = lane & 15;
    int ldcol = (lane >> 4) * 8;

    float acc[2][4][4] = {};

    auto loadTile = [&](int s, int k0) {
        __half* Ab = As + s * 128 * GS;
        __half* Bd = Bs + s * 64 * GS;
#pragma unroll
        for (int i = 0; i < 2; i++) {
            int id = tid + 256 * i;
            int row = id >> 2, f = id & 3;
            cp16(&Ab[row * GS + f * 8], &A[(size_t)(m0 + row) * K + k0 + f * 8]);
        }
        {
            int row = tid >> 2, f = tid & 3;
            cp16(&Bd[row * GS + f * 8], &W[(size_t)(n0 + row) * K + k0 + f * 8]);
        }
    };

    int KT = K >> 5;
    loadTile(0, 0);
    CP_COMMIT();
    if (KT > 1) { loadTile(1, 32); CP_COMMIT(); }
    for (int kt = 0; kt < KT; kt++) {
        if (kt + 1 < KT) { CP_WAIT(1); } else { CP_WAIT(0); }
        __syncthreads();
        int s = kt % 3;
        const __half* Ab = As + s * 128 * GS;
        const __half* Bd = Bs + s * 64 * GS;
#pragma unroll
        for (int ks = 0; ks < 2; ks++) {
            uint32_t af[2][4];
#pragma unroll
            for (int mi = 0; mi < 2; mi++)
                LDSM_X4(af[mi][0], af[mi][1], af[mi][2], af[mi][3],
                        saddr(&Ab[(wm + mi * 16 + ldrow) * GS + ks * 16 + ldcol]));
#pragma unroll
            for (int nb = 0; nb < 2; nb++) {
                uint32_t b0, b1, b2, b3;
                LDSM_X4(b0, b1, b2, b3,
                        saddr(&Bd[(wn + nb * 16 + ldrow) * GS + ks * 16 + ldcol]));
#pragma unroll
                for (int mi = 0; mi < 2; mi++) {
                    MMA_F16(acc[mi][nb * 2],     af[mi][0], af[mi][1], af[mi][2], af[mi][3], b0, b2);
                    MMA_F16(acc[mi][nb * 2 + 1], af[mi][0], af[mi][1], af[mi][2], af[mi][3], b1, b3);
                }
            }
        }
        if (kt + 2 < KT) { loadTile((kt + 2) % 3, (kt + 2) << 5); CP_COMMIT(); }
    }

    // epilogue
#pragma unroll
    for (int mi = 0; mi < 2; mi++) {
#pragma unroll
        for (int ni = 0; ni < 4; ni++) {
            int r = m0 + wm + mi * 16 + lg;
            int c = n0 + wn + ni * 8 + lt * 2;
            float b0 = bias[c], b1 = bias[c + 1];
#pragma unroll
            for (int half_ = 0; half_ < 2; half_++) {
                int rr = r + half_ * 8;
                float v0 = (acc[mi][ni][half_ * 2 + 0] + b0) * alpha;
                float v1 = (acc[mi][ni][half_ * 2 + 1] + b1) * alpha;
                if (epi == EPI_GELU) {
                    v0 = 0.5f * v0 * (1.0f + erff(v0 * 0.70710678118654752f));
                    v1 = 0.5f * v1 * (1.0f + erff(v1 * 0.70710678118654752f));
                } else if (epi == EPI_THETA) {
                    int l = rr & (L - 1);
                    int d0 = c & 31;
                    const float* sp = sn + l * KD + d0;
                    const float* cq = cs + l * KD + d0;
                    float s0 = sp[0], s1 = sp[1];
                    float c0 = cq[0], c1 = cq[1];
                    float o0 = v0 * c0 - v1 * s0;
                    float o1 = v1 * c1 + v0 * s1;
                    v0 = o0; v1 = o1;
                }
                if (res) {
                    v0 += res[(size_t)rr * N + c];
                    v1 += res[(size_t)rr * N + c + 1];
                }
                if (C)
                    *(float2*)&C[(size_t)rr * N + c] = make_float2(v0, v1);
                if (Ch)
                    *(__half2*)&Ch[(size_t)rr * N + c] = __floats2half2_rn(v0, v1);
            }
        }
    }
}

__global__ __launch_bounds__(256) void gemm_kernel(
        const __half* __restrict__ A, const __half* __restrict__ W,
        const float* __restrict__ bias, const float* __restrict__ res,
        float* __restrict__ C, __half* __restrict__ Ch,
        int M, int N, int K, float alpha, int epi) {
    __shared__ __align__(16) __half As[3 * 128 * GS];
    __shared__ __align__(16) __half Bs[3 * 64 * GS];
    gemm16_core(A, W, bias, res, C, Ch, M, N, K, alpha, epi, nullptr, nullptr, As, Bs);
}

__global__ __launch_bounds__(256) void qkv_gemm_kernel(
        const __half* __restrict__ HN, const __half* __restrict__ Wh,
        const float* __restrict__ bq, const float* __restrict__ bk,
        const float* __restrict__ bv,
        __half* __restrict__ QH, __half* __restrict__ KH,
        __half* __restrict__ VH,
        const float* __restrict__ sn, const float* __restrict__ cs) {
    __shared__ __align__(16) __half As[3 * 128 * GS];
    __shared__ __align__(16) __half Bs[3 * 64 * GS];
    int z = blockIdx.z;
    const __half* W = Wh + (z == 0 ? WH_WQ : z == 1 ? WH_WK : WH_WV);
    const float* bias = (z == 0) ? bq : (z == 1) ? bk : bv;
    __half* Ch = (z == 0) ? QH : (z == 1) ? KH : VH;
    float alpha = (z == 1) ? SCALING : 1.f;
    int epi = (z == 2) ? EPI_NONE : EPI_THETA;
    gemm16_core(HN, W, bias, nullptr, nullptr, Ch, Bb * L, E, E, alpha, epi, sn, cs, As, Bs);
}

__global__ __launch_bounds__(256) void ckv_gemm_kernel(
        const __half* __restrict__ XH, const __half* __restrict__ Wh,
        const float* __restrict__ ca_in_b,
        __half* __restrict__ CKH, __half* __restrict__ CVH) {
    __shared__ __align__(16) __half As[3 * 128 * GS];
    __shared__ __align__(16) __half Bs[3 * 64 * GS];
    int z = blockIdx.z;
    const __half* W = Wh + WH_CAIN + (size_t)(z + 1) * E * E;
    const float* bias = ca_in_b + (z + 1) * E;
    __half* Ch = z ? CVH : CKH;
    gemm16_core(XH, W, bias, nullptr, nullptr, Ch, Bb * L, E, E, 1.f, EPI_NONE,
                nullptr, nullptr, As, Bs);
}

// ---------------- fused dwconv3x3(+in) + LN1 --------------------------
__global__ void dwconv3_ln_kernel(const float* __restrict__ in,
                                  const float* __restrict__ w,
                                  const float* __restrict__ bias,
                                  const float* __restrict__ g,
                                  const float* __restrict__ bln,
                                  float* __restrict__ X1,
                                  __half* __restrict__ HN) {
    int c = threadIdx.x;
    int wx = blockIdx.x, hy = blockIdx.y, b = blockIdx.z;
    float acc = bias[c];
#pragma unroll
    for (int kh = 0; kh < 3; kh++) {
        int y = hy + kh - 1;
        if (y < 0 || y >= HH) continue;
#pragma unroll
        for (int kw = 0; kw < 3; kw++) {
            int xx = wx + kw - 1;
            if (xx < 0 || xx >= WW) continue;
            acc += in[(((size_t)b * HH + y) * WW + xx) * E + c] *
                   w[c * 9 + kh * 3 + kw];
        }
    }
    size_t o = (((size_t)b * HH + hy) * WW + wx) * E + c;
    float v = in[o] + acc;
    X1[o] = v;
    __shared__ float red[2];
    blk_reduce2(v, v * v, red, c);
    float m = red[0] * (1.0f / E);
    float var = red[1] * (1.0f / E) - m * m;
    float inv = rsqrtf(var + 1e-6f);
    HN[o] = __float2half((v - m) * inv * g[c] + bln[c]);
}

// ---------------- dwconv 5x5: fp16 in, fp32 out, 4 px/thread -------------
__global__ __launch_bounds__(256) void dwconv5_kernel(
        const __half* __restrict__ VH, const float* __restrict__ w,
        const float* __restrict__ bias, float* __restrict__ out) {
    int c = threadIdx.x;
    int x0 = blockIdx.x * 4, hy = blockIdx.y, b = blockIdx.z;
    float wreg[25];
#pragma unroll
    for (int i = 0; i < 25; i++) wreg[i] = w[c * 25 + i];
    float bz = bias[c];
    float acc[4] = {bz, bz, bz, bz};
#pragma unroll
    for (int kh = 0; kh < 5; kh++) {
        int y = hy + kh - 2;
        if (y < 0 || y >= HH) continue;
        const __half* rbase = VH + (((size_t)b * HH + y) * WW) * E + c;
#pragma unroll
        for (int kw = 0; kw < 8; kw++) {
            int xx = x0 + kw - 2;
            if (xx < 0 || xx >= WW) continue;
            float v = __half2float(rbase[(size_t)xx * E]);
            int dx = kw - 2;
#pragma unroll
            for (int j = 0; j < 4; j++) {
                int kwi = dx - j + 2;
                if (kwi >= 0 && kwi < 5)
                    acc[j] += v * wreg[kh * 5 + kwi];
            }
        }
    }
    size_t obase = (((size_t)b * HH + hy) * WW + x0) * E + c;
#pragma unroll
    for (int j = 0; j < 4; j++)
        out[obase + (size_t)j * E] = acc[j];
}

// ---------------- AOH += LEPE (join kernel for the dwconv5 branch) -------
__global__ void add_lepe_kernel(__half* __restrict__ AOH,
                                const float* __restrict__ LEPE) {
    int idx = blockIdx.x * 256 + threadIdx.x;
    float v = __half2float(AOH[idx]) + LEPE[idx];
    AOH[idx] = __float2half(v);
}

// ---------------- layernorm (fp32 in, fp16 out) ------------------------
__global__ void ln_kernel(const float* __restrict__ in,
                          const float* __restrict__ g,
                          const float* __restrict__ b,
                          __half* __restrict__ out) {
    int row = blockIdx.x;
    int t = threadIdx.x;
    float v = in[(size_t)row * E + t];
    __shared__ float red[2];
    blk_reduce2(v, v * v, red, t);
    float m = red[0] * (1.0f / E);
    float var = red[1] * (1.0f / E) - m * m;
    float inv = rsqrtf(var + 1e-6f);
    out[(size_t)row * E + t] = __float2half((v - m) * inv * g[t] + b[t]);
}

// ---------------- fp16 flash attention, fixed-max softmax ----------------
// 64 queries/block (16 per warp). Mask preloaded before S-mma.
// nsplit>1: unnormalized partials (PO fp32, PL row sums).
#define KVS 40
#define PSS 72
__global__ __launch_bounds__(128) void attn_f16_kernel(
        const __half* __restrict__ Q, const __half* __restrict__ Kt,
        const __half* __restrict__ V,
        const float* __restrict__ mask,
        __half* __restrict__ O, float* __restrict__ PO, float* __restrict__ PL,
        int Lq, int Lk, float scale, int nsplit) {
    __shared__ __align__(16) __half Qs[64 * KVS];
    __shared__ __align__(16) __half Ks[3][64 * KVS];
    __shared__ __align__(16) __half Vs[3][64 * KVS];
    __shared__ __align__(16) __half Ps[64 * PSS];

    int tid = threadIdx.x;
    int w = tid >> 5, lane = tid & 31;
    int lg = lane >> 2, lt = lane & 3;
    int h = blockIdx.y, b = blockIdx.z;
    int qtiles = Lq >> 6;
    int split = blockIdx.x / qtiles;
    int q0 = (blockIdx.x - split * qtiles) * 64;
    int wm = w * 16;
    int ldrow = lane & 15;
    int ldcol = (lane >> 4) * 8;

    int NJ = (Lk >> 6) / nsplit;
    int jbase = split * NJ;

    auto loadTile = [&](__half* dst, const __half* src) {
#pragma unroll
        for (int i = 0; i < 2; i++) {
            int id = tid + 128 * i;
            int row = id >> 2, gr = id & 3;
            cp16(dst + row * KVS + gr * 8, src + (size_t)row * E + gr * 8);
        }
    };
    auto loadKV = [&](int s, int chunk) {
        loadTile(Ks[s], Kt + ((size_t)(b * Lk + (chunk << 6))) * E + h * KD);
        loadTile(Vs[s], V  + ((size_t)(b * Lk + (chunk << 6))) * E + h * KD);
        CP_COMMIT();
    };

    loadTile(Qs, Q + ((size_t)(b * Lq + q0)) * E + h * KD);
    CP_COMMIT();
    loadKV(0, jbase);
    if (NJ > 1) loadKV(1, jbase + 1);
    CP_WAIT(2);
    __syncthreads();

    uint32_t qf[2][4];
#pragma unroll
    for (int ks = 0; ks < 2; ks++)
        LDSM_X4(qf[ks][0], qf[ks][1], qf[ks][2], qf[ks][3],
                saddr(&Qs[(wm + ldrow) * KVS + ks * 16 + ldcol]));

    float ps0 = 0.f, ps1 = 0.f;
    float oacc[4][4] = {};
    const float* mbase = mask ? (mask + ((size_t)h * Lk + q0) * Lk) : nullptr;
    float sl2 = scale * LOG2E;

    for (int jt = 0; jt < NJ; jt++) {
        int j0 = (jbase + jt) << 6;
        if (jt + 1 < NJ) { CP_WAIT(1); } else { CP_WAIT(0); }
        __syncthreads();
        int s = jt % 3;

        // preload mask BEFORE the S-mma (LDG hides under tensor ops)
        float2 mv[8][2];
        if (mbase) {
            int r0 = wm + lg, r1 = wm + 8 + lg;
#pragma unroll
            for (int ni = 0; ni < 8; ni++) {
                int c = j0 + ni * 8 + lt * 2;
                mv[ni][0] = *(const float2*)&mbase[(size_t)r0 * Lk + c];
                mv[ni][1] = *(const float2*)&mbase[(size_t)r1 * Lk + c];
            }
        }

        float sacc[8][4];
#pragma unroll
        for (int ni = 0; ni < 8; ni++)
#pragma unroll
            for (int c = 0; c < 4; c++) sacc[ni][c] = 0.f;
#pragma unroll
        for (int ks = 0; ks < 2; ks++) {
#pragma unroll
            for (int nb = 0; nb < 4; nb++) {
                uint32_t r0, r1, r2, r3;
                LDSM_X4(r0, r1, r2, r3,
                        saddr(&Ks[s][(nb * 16 + ldrow) * KVS + ks * 16 + ldcol]));
                MMA_F16(sacc[2 * nb],     qf[ks][0], qf[ks][1], qf[ks][2], qf[ks][3], r0, r2);
                MMA_F16(sacc[2 * nb + 1], qf[ks][0], qf[ks][1], qf[ks][2], qf[ks][3], r1, r3);
            }
        }

        // exp (fixed max = 0) + P store + running row sums
#pragma unroll
        for (int ni = 0; ni < 8; ni++) {
            float p0, p1, p2, p3;
            if (mbase) {
                p0 = exp2f((sacc[ni][0] + mv[ni][0].x) * LOG2E);
                p1 = exp2f((sacc[ni][1] + mv[ni][0].y) * LOG2E);
                p2 = exp2f((sacc[ni][2] + mv[ni][1].x) * LOG2E);
                p3 = exp2f((sacc[ni][3] + mv[ni][1].y) * LOG2E);
            } else {
                p0 = exp2f(sacc[ni][0] * sl2);
                p1 = exp2f(sacc[ni][1] * sl2);
                p2 = exp2f(sacc[ni][2] * sl2);
                p3 = exp2f(sacc[ni][3] * sl2);
            }
            ps0 += p0 + p1;
            ps1 += p2 + p3;
            int c = ni * 8 + lt * 2;
            *(__half2*)&Ps[(wm + lg) * PSS + c]     = __floats2half2_rn(p0, p1);
            *(__half2*)&Ps[(wm + 8 + lg) * PSS + c] = __floats2half2_rn(p2, p3);
        }
        __syncwarp();

#pragma unroll
        for (int ks = 0; ks < 4; ks++) {
            uint32_t pa0, pa1, pa2, pa3;
            LDSM_X4(pa0, pa1, pa2, pa3,
                    saddr(&Ps[(wm + ldrow) * PSS + ks * 16 + ldcol]));
            uint32_t v0, v1, v2, v3;
            LDSM_X4T(v0, v1, v2, v3,
                     saddr(&Vs[s][(ks * 16 + ldrow) * KVS + 0 + ldcol]));
            uint32_t u0, u1, u2, u3;
            LDSM_X4T(u0, u1, u2, u3,
                     saddr(&Vs[s][(ks * 16 + ldrow) * KVS + 16 + ldcol]));
            MMA_F16(oacc[0], pa0, pa1, pa2, pa3, v0, v1);
            MMA_F16(oacc[1], pa0, pa1, pa2, pa3, v2, v3);
            MMA_F16(oacc[2], pa0, pa1, pa2, pa3, u0, u1);
            MMA_F16(oacc[3], pa0, pa1, pa2, pa3, u2, u3);
        }
        if (jt + 2 < NJ) loadKV((jt + 2) % 3, jbase + jt + 2);
    }

    // row-sum reduce across the quad
    ps0 += __shfl_xor_sync(0xffffffff, ps0, 1);
    ps0 += __shfl_xor_sync(0xffffffff, ps0, 2);
    ps1 += __shfl_xor_sync(0xffffffff, ps1, 1);
    ps1 += __shfl_xor_sync(0xffffffff, ps1, 2);

    int r0 = q0 + wm + lg, r1 = r0 + 8;
    if (nsplit == 1) {
        float inv0 = 1.f / ps0, inv1 = 1.f / ps1;
#pragma unroll
        for (int ni = 0; ni < 4; ni++) {
            int c = h * KD + ni * 8 + lt * 2;
            *(__half2*)&O[((size_t)(b * Lq + r0)) * E + c] =
                __floats2half2_rn(oacc[ni][0] * inv0, oacc[ni][1] * inv0);
            *(__half2*)&O[((size_t)(b * Lq + r1)) * E + c] =
                __floats2half2_rn(oacc[ni][2] * inv1, oacc[ni][3] * inv1);
        }
    } else {
        size_t base = (size_t)split * Bb * Lq;
#pragma unroll
        for (int ni = 0; ni < 4; ni++) {
            int c = h * KD + ni * 8 + lt * 2;
            *(float2*)&PO[(base + b * Lq + r0) * E + c] =
                make_float2(oacc[ni][0], oacc[ni][1]);
            *(float2*)&PO[(base + b * Lq + r1) * E + c] =
                make_float2(oacc[ni][2], oacc[ni][3]);
        }
        if (lt == 0) {
            size_t plb = (((size_t)split * Bb + b) * HEADS + h) * Lq;
            PL[plb + r0] = ps0;
            PL[plb + r1] = ps1;
        }
    }
}

// ---------------- split-KV reduce: out = Σpo / Σl ------------------------
__global__ void attn_reduce_kernel(const float* __restrict__ PO,
                                   const float* __restrict__ PL,
                                   __half* __restrict__ out) {
    int idx = blockIdx.x * 256 + threadIdx.x;      // over Bb*NQ*E
    int e = idx & (E - 1);
    int bq = idx >> 8;
    int q = bq & (NQ - 1);
    int b = bq >> 6;
    int h = e >> 5;
    float num = 0.f, den = 0.f;
#pragma unroll
    for (int s = 0; s < NSPLIT; s++) {
        num += PO[((size_t)s * Bb * NQ + bq) * E + e];
        den += PL[(((size_t)s * Bb + b) * HEADS + h) * NQ + q];
    }
    out[idx] = __float2half(num / den);
}

// ---------------- launcher ----------------------------------------------
extern "C" void kernel_launch(void* const* d_in, const int* in_sizes, int n_in,
                              void* d_out, int out_size) {
    const float* x       = (const float*)d_in[0];
    const float* queries = (const float*)d_in[1];
    const float* sn      = (const float*)d_in[2];
    const float* cs      = (const float*)d_in[3];
    const float* mask    = (const float*)d_in[4];
    const float* ln1_g   = (const float*)d_in[5];
    const float* ln1_b   = (const float*)d_in[6];
    const float* ln2_g   = (const float*)d_in[7];
    const float* ln2_b   = (const float*)d_in[8];
    const float* wq      = (const float*)d_in[9];
    const float* bq      = (const float*)d_in[10];
    const float* wk      = (const float*)d_in[11];
    const float* bk      = (const float*)d_in[12];
    const float* wv      = (const float*)d_in[13];
    const float* bv      = (const float*)d_in[14];
    const float* lepe_w  = (const float*)d_in[15];
    const float* lepe_b  = (const float*)d_in[16];
    const float* wo      = (const float*)d_in[17];
    const float* bo      = (const float*)d_in[18];
    const float* fc1_w   = (const float*)d_in[19];
    const float* fc1_b   = (const float*)d_in[20];
    const float* fc2_w   = (const float*)d_in[21];
    const float* fc2_b   = (const float*)d_in[22];
    const float* pos_w   = (const float*)d_in[23];
    const float* pos_b   = (const float*)d_in[24];
    const float* ca_in_w = (const float*)d_in[25];
    const float* ca_in_b = (const float*)d_in[26];
    const float* ca_out_w= (const float*)d_in[27];
    const float* ca_out_b= (const float*)d_in[28];

    void* sp = nullptr;
    cudaGetSymbolAddress(&sp, g_scratch);
    float* S = (float*)sp;
    float* X1   = S + OFF_X1;
    float* LEPE = S + OFF_LEPE;
    float* X2   = S + OFF_X2;
    float* Q2   = S + OFF_Q2;
    float* PO   = S + OFF_PO;
    float* PL   = S + OFF_PL;
    __half* HN   = (__half*)(S + OFF_HN);
    __half* QH   = (__half*)(S + OFF_QH);
    __half* KH   = (__half*)(S + OFF_KH);
    __half* VH   = (__half*)(S + OFF_VH);
    __half* AOH  = (__half*)(S + OFF_AOH);
    __half* XH   = (__half*)(S + OFF_XH);
    __half* CKH  = (__half*)(S + OFF_CKH);
    __half* CVH  = (__half*)(S + OFF_CVH);
    __half* FF   = (__half*)(S + OFF_FF);
    __half* CQH  = (__half*)(S + OFF_CQH);
    __half* CAOH = (__half*)(S + OFF_CAOH);
    __half* QLN  = (__half*)(S + OFF_QLN);
    __half* QLN2 = (__half*)(S + OFF_QLN2);
    __half* QFF  = (__half*)(S + OFF_QFF);
    __half* WHb  = (__half*)(S + OFF_WH);

    float* OX = (float*)d_out;
    float* OQ = OX + (size_t)Bb * L * E;

    const int MTOK = Bb * L;   // 8192
    const int MQ   = Bb * NQ;  // 512
    dim3 sp3(WW, HH, Bb);
    dim3 c5(WW / 4, HH, Bb);

    static cudaStream_t s2 = nullptr, s3 = nullptr;
    static cudaEvent_t ev0 = nullptr, evW = nullptr, evQ = nullptr,
                       evV = nullptr, evL = nullptr;
    if (!s2) {
        cudaStreamCreateWithFlags(&s2, cudaStreamNonBlocking);
        cudaStreamCreateWithFlags(&s3, cudaStreamNonBlocking);
        cudaEventCreateWithFlags(&ev0, cudaEventDisableTiming);
        cudaEventCreateWithFlags(&evW, cudaEventDisableTiming);
        cudaEventCreateWithFlags(&evQ, cudaEventDisableTiming);
        cudaEventCreateWithFlags(&evV, cudaEventDisableTiming);
        cudaEventCreateWithFlags(&evL, cudaEventDisableTiming);
    }

    // fork side stream s2: weights conversion + queries prologue
    cudaEventRecord(ev0, 0);
    cudaStreamWaitEvent(s2, ev0, 0);
    wconv_kernel<<<dim3(128, 8), 256, 0, s2>>>(wq, wk, wv, wo, fc1_w, fc2_w,
                                               ca_in_w, ca_out_w, WHb);
    cudaEventRecord(evW, s2);
    ln_kernel<<<MQ, 256, 0, s2>>>(queries, ln1_g, ln1_b, QLN);
    gemm_kernel<<<dim3(E/64, MQ/128), 256, 0, s2>>>(
        QLN, WHb + WH_CAIN, ca_in_b, nullptr, nullptr, CQH, MQ, E, E, 1.f, EPI_NONE);
    cudaEventRecord(evQ, s2);

    // main: dwconv3 + LN1 (independent of weights)
    dwconv3_ln_kernel<<<sp3, 256>>>(x, pos_w, pos_b, ln1_g, ln1_b, X1, HN);
    // qkv needs the fp16 weights
    cudaStreamWaitEvent(0, evW, 0);
    qkv_gemm_kernel<<<dim3(E/64, MTOK/128, 3), 256>>>(
        HN, WHb, bq, bk, bv, QH, KH, VH, sn, cs);
    cudaEventRecord(evV, 0);

    // fork s3: dwconv5 runs concurrently with self-attention
    cudaStreamWaitEvent(s3, evV, 0);
    dwconv5_kernel<<<c5, 256, 0, s3>>>(VH, lepe_w, lepe_b, LEPE);
    cudaEventRecord(evL, s3);

    // self attention (pure, no addend)
    attn_f16_kernel<<<dim3(L/64, HEADS, Bb), 128>>>(
        QH, KH, VH, mask, AOH, nullptr, nullptr, L, L, 1.f, 1);
    // join dwconv5, then AOH += LEPE
    cudaStreamWaitEvent(0, evL, 0);
    add_lepe_kernel<<<(Bb * L * E) / 256, 256>>>(AOH, LEPE);

    // x2 = x1 + aoh @ wo^T + bo
    gemm_kernel<<<dim3(E/64, MTOK/128), 256>>>(AOH, WHb + WH_WO, bo, X1, X2, nullptr, MTOK, E, E, 1.f, EPI_NONE);
    // FFN on x
    ln_kernel<<<MTOK, 256>>>(X2, ln2_g, ln2_b, HN);
    gemm_kernel<<<dim3(FFN/64, MTOK/128), 256>>>(HN, WHb + WH_FC1, fc1_b, nullptr, nullptr, FF, MTOK, FFN, E, 1.f, EPI_GELU);
    gemm_kernel<<<dim3(E/64, MTOK/128), 256>>>(FF, WHb + WH_FC2, fc2_b, X2, OX, XH, MTOK, E, FFN, 1.f, EPI_NONE);
    // cross attention (split-KV); CQH comes from s2
    ckv_gemm_kernel<<<dim3(E/64, MTOK/128, 2), 256>>>(XH, WHb, ca_in_b, CKH, CVH);
    cudaStreamWaitEvent(0, evQ, 0);
    attn_f16_kernel<<<dim3(NSPLIT, HEADS, Bb), 128>>>(
        CQH, CKH, CVH, nullptr, nullptr, PO, PL, NQ, L, SCALING, NSPLIT);
    attn_reduce_kernel<<<(Bb * NQ * E) / 256, 256>>>(PO, PL, CAOH);
    gemm_kernel<<<dim3(E/64, MQ/128), 256>>>(CAOH, WHb + WH_CAOUT, ca_out_b, queries, Q2, nullptr, MQ, E, E, 1.f, EPI_NONE);
    // FFN on queries
    ln_kernel<<<MQ, 256>>>(Q2, ln2_g, ln2_b, QLN2);
    gemm_kernel<<<dim3(FFN/64, MQ/128), 256>>>(QLN2, WHb + WH_FC1, fc1_b, nullptr, nullptr, QFF, MQ, FFN, E, 1.f, EPI_GELU);
    gemm_kernel<<<dim3(E/64, MQ/128), 256>>>(QFF, WHb + WH_FC2, fc2_b, Q2, OQ, nullptr, MQ, E, FFN, 1.f, EPI_NONE);
}

// round 15
// speedup vs baseline: 1.0550x; 1.0227x over previous
#include <cuda_runtime.h>
#include <cuda_fp16.h>
#include <math.h>
#include <stdint.h>

#define Bb 8
#define HH 32
#define WW 32
#define E 256
#define HEADS 8
#define KD 32
#define FFN 1024
#define NQ 64
#define L 1024
#define SCALING 0.17677669529663687f
#define LOG2E 1.4426950408889634f
#define NSPLIT 4

#define EPI_NONE 0
#define EPI_GELU 1
#define EPI_THETA 2

// ---------------- scratch arena (float units) ----------------
#define SZ_TOK ((size_t)Bb * L * E)
#define SZ_QTK ((size_t)Bb * NQ * E)
#define OFF_X1    ((size_t)0)
#define OFF_LEPE  (OFF_X1 + SZ_TOK)
#define OFF_X2    (OFF_LEPE + SZ_TOK)
#define OFF_Q2    (OFF_X2 + SZ_TOK)
#define OFF_HN    (OFF_Q2 + SZ_QTK)
#define OFF_QH    (OFF_HN + SZ_TOK / 2)
#define OFF_KH    (OFF_QH + SZ_TOK / 2)
#define OFF_VH    (OFF_KH + SZ_TOK / 2)
#define OFF_AOH   (OFF_VH + SZ_TOK / 2)
#define OFF_XH    (OFF_AOH + SZ_TOK / 2)
#define OFF_CKH   (OFF_XH + SZ_TOK / 2)
#define OFF_CVH   (OFF_CKH + SZ_TOK / 2)
#define OFF_FF    (OFF_CVH + SZ_TOK / 2)
#define OFF_CQH   (OFF_FF + (size_t)Bb * L * FFN / 2)
#define OFF_CAOH  (OFF_CQH + SZ_QTK / 2)
#define OFF_QLN   (OFF_CAOH + SZ_QTK / 2)
#define OFF_QLN2  (OFF_QLN + SZ_QTK / 2)
#define OFF_QFF   (OFF_QLN2 + SZ_QTK / 2)
#define OFF_WH    (OFF_QFF + (size_t)Bb * NQ * FFN / 2)
#define OFF_PO    (OFF_WH + 524288)
#define OFF_PL    (OFF_PO + (size_t)NSPLIT * SZ_QTK)
#define SCRATCH_TOTAL (OFF_PL + (size_t)NSPLIT * Bb * HEADS * NQ)

__device__ float g_scratch[SCRATCH_TOTAL];

// fp16 weight arena offsets (half units)
#define WH_WQ    0
#define WH_WK    65536
#define WH_WV    131072
#define WH_WO    196608
#define WH_FC1   262144
#define WH_FC2   524288
#define WH_CAIN  786432
#define WH_CAOUT 983040

// ---------------- helpers ----------------
__device__ __forceinline__ void cp16(void* dst, const void* src) {
    uint32_t d = (uint32_t)__cvta_generic_to_shared(dst);
    asm volatile("cp.async.cg.shared.global [%0], [%1], 16;" :: "r"(d), "l"(src));
}
#define CP_COMMIT() asm volatile("cp.async.commit_group;" ::: "memory")
#define CP_WAIT(N)  asm volatile("cp.async.wait_group %0;" :: "n"(N) : "memory")

__device__ __forceinline__ uint32_t saddr(const void* p) {
    return (uint32_t)__cvta_generic_to_shared(p);
}

#define LDSM_X4(r0, r1, r2, r3, a)                                          \
    asm volatile("ldmatrix.sync.aligned.m8n8.x4.shared.b16 {%0,%1,%2,%3}, [%4];" \
        : "=r"(r0), "=r"(r1), "=r"(r2), "=r"(r3) : "r"(a))
#define LDSM_X4T(r0, r1, r2, r3, a)                                         \
    asm volatile("ldmatrix.sync.aligned.m8n8.x4.trans.shared.b16 {%0,%1,%2,%3}, [%4];" \
        : "=r"(r0), "=r"(r1), "=r"(r2), "=r"(r3) : "r"(a))

#define MMA_F16(acc, a0, a1, a2, a3, b0, b1)                                \
    asm volatile(                                                           \
        "mma.sync.aligned.m16n8k16.row.col.f32.f16.f16.f32 "                \
        "{%0,%1,%2,%3}, {%4,%5,%6,%7}, {%8,%9}, {%0,%1,%2,%3};"             \
        : "+f"(acc[0]), "+f"(acc[1]), "+f"(acc[2]), "+f"(acc[3])            \
        : "r"(a0), "r"(a1), "r"(a2), "r"(a3), "r"(b0), "r"(b1))

// warp+block reduction of (sum, sumsq)  (used by dwconv3_ln)
__device__ __forceinline__ void blk_reduce2(float v, float q, float* out2,
                                            int tid) {
    __shared__ float ws[8], wq[8];
#pragma unroll
    for (int o = 16; o > 0; o >>= 1) {
        v += __shfl_xor_sync(0xffffffff, v, o);
        q += __shfl_xor_sync(0xffffffff, q, o);
    }
    if ((tid & 31) == 0) { ws[tid >> 5] = v; wq[tid >> 5] = q; }
    __syncthreads();
    if (tid < 32) {
        float a = (tid < 8) ? ws[tid] : 0.f;
        float b = (tid < 8) ? wq[tid] : 0.f;
#pragma unroll
        for (int o = 4; o > 0; o >>= 1) {
            a += __shfl_xor_sync(0xffffffff, a, o);
            b += __shfl_xor_sync(0xffffffff, b, o);
        }
        if (tid == 0) { out2[0] = a; out2[1] = b; }
    }
    __syncthreads();
}

// ---------------- weight fp32 -> fp16 conversion ----------------
__global__ void wconv_kernel(const float* __restrict__ wq, const float* __restrict__ wk,
                             const float* __restrict__ wv, const float* __restrict__ wo,
                             const float* __restrict__ fc1, const float* __restrict__ fc2,
                             const float* __restrict__ cain, const float* __restrict__ caout,
                             __half* __restrict__ Wh) {
    const int sizes[8] = {65536, 65536, 65536, 65536, 262144, 262144, 196608, 65536};
    const int offs[8]  = {WH_WQ, WH_WK, WH_WV, WH_WO, WH_FC1, WH_FC2, WH_CAIN, WH_CAOUT};
    int z = blockIdx.y;
    const float* src = z == 0 ? wq : z == 1 ? wk : z == 2 ? wv : z == 3 ? wo
                     : z == 4 ? fc1 : z == 5 ? fc2 : z == 6 ? cain : caout;
    int n = sizes[z];
    __half* dst = Wh + offs[z];
    for (int i = blockIdx.x * 256 + threadIdx.x; i < n; i += gridDim.x * 256)
        dst[i] = __float2half(src[i]);
}

// ---------------- fp16 GEMM core (3-stage pipeline, 128x64 tile) ---------
#define GS 40
__device__ __forceinline__ void gemm16_core(
        const __half* __restrict__ A, const __half* __restrict__ W,
        const float* __restrict__ bias, const float* __restrict__ res,
        float* __restrict__ C, __half* __restrict__ Ch,
        int M, int N, int K, float alpha, int epi,
        const float* __restrict__ sn, const float* __restrict__ cs,
        __half* As, __half* Bs) {
    int tid = threadIdx.x;
    int w = tid >> 5, lane = tid & 31;
    int wm = (w & 3) * 32, wn = (w >> 2) * 32;
    int m0 = blockIdx.y * 128, n0 = blockIdx.x * 64;
    int lg = lane >> 2, lt = lane & 3;
    int ldrow = lane & 15;
    int ldcol = (lane >> 4) * 8;

    float acc[2][4][4] = {};

    auto loadTile = [&](int s, int k0) {
        __half* Ab = As + s * 128 * GS;
        __half* Bd = Bs + s * 64 * GS;
#pragma unroll
        for (int i = 0; i < 2; i++) {
            int id = tid + 256 * i;
            int row = id >> 2, f = id & 3;
            cp16(&Ab[row * GS + f * 8], &A[(size_t)(m0 + row) * K + k0 + f * 8]);
        }
        {
            int row = tid >> 2, f = tid & 3;
            cp16(&Bd[row * GS + f * 8], &W[(size_t)(n0 + row) * K + k0 + f * 8]);
        }
    };

    int KT = K >> 5;
    loadTile(0, 0);
    CP_COMMIT();
    if (KT > 1) { loadTile(1, 32); CP_COMMIT(); }
    for (int kt = 0; kt < KT; kt++) {
        if (kt + 1 < KT) { CP_WAIT(1); } else { CP_WAIT(0); }
        __syncthreads();
        int s = kt % 3;
        const __half* Ab = As + s * 128 * GS;
        const __half* Bd = Bs + s * 64 * GS;
#pragma unroll
        for (int ks = 0; ks < 2; ks++) {
            uint32_t af[2][4];
#pragma unroll
            for (int mi = 0; mi < 2; mi++)
                LDSM_X4(af[mi][0], af[mi][1], af[mi][2], af[mi][3],
                        saddr(&Ab[(wm + mi * 16 + ldrow) * GS + ks * 16 + ldcol]));
#pragma unroll
            for (int nb = 0; nb < 2; nb++) {
                uint32_t b0, b1, b2, b3;
                LDSM_X4(b0, b1, b2, b3,
                        saddr(&Bd[(wn + nb * 16 + ldrow) * GS + ks * 16 + ldcol]));
#pragma unroll
                for (int mi = 0; mi < 2; mi++) {
                    MMA_F16(acc[mi][nb * 2],     af[mi][0], af[mi][1], af[mi][2], af[mi][3], b0, b2);
                    MMA_F16(acc[mi][nb * 2 + 1], af[mi][0], af[mi][1], af[mi][2], af[mi][3], b1, b3);
                }
            }
        }
        if (kt + 2 < KT) { loadTile((kt + 2) % 3, (kt + 2) << 5); CP_COMMIT(); }
    }

    // epilogue
#pragma unroll
    for (int mi = 0; mi < 2; mi++) {
#pragma unroll
        for (int ni = 0; ni < 4; ni++) {
            int r = m0 + wm + mi * 16 + lg;
            int c = n0 + wn + ni * 8 + lt * 2;
            float b0 = bias[c], b1 = bias[c + 1];
#pragma unroll
            for (int half_ = 0; half_ < 2; half_++) {
                int rr = r + half_ * 8;
                float v0 = (acc[mi][ni][half_ * 2 + 0] + b0) * alpha;
                float v1 = (acc[mi][ni][half_ * 2 + 1] + b1) * alpha;
                if (epi == EPI_GELU) {
                    v0 = 0.5f * v0 * (1.0f + erff(v0 * 0.70710678118654752f));
                    v1 = 0.5f * v1 * (1.0f + erff(v1 * 0.70710678118654752f));
                } else if (epi == EPI_THETA) {
                    int l = rr & (L - 1);
                    int d0 = c & 31;
                    const float* sp = sn + l * KD + d0;
                    const float* cq = cs + l * KD + d0;
                    float s0 = sp[0], s1 = sp[1];
                    float c0 = cq[0], c1 = cq[1];
                    float o0 = v0 * c0 - v1 * s0;
                    float o1 = v1 * c1 + v0 * s1;
                    v0 = o0; v1 = o1;
                }
                if (res) {
                    v0 += res[(size_t)rr * N + c];
                    v1 += res[(size_t)rr * N + c + 1];
                }
                if (C)
                    *(float2*)&C[(size_t)rr * N + c] = make_float2(v0, v1);
                if (Ch)
                    *(__half2*)&Ch[(size_t)rr * N + c] = __floats2half2_rn(v0, v1);
            }
        }
    }
}

__global__ __launch_bounds__(256) void gemm_kernel(
        const __half* __restrict__ A, const __half* __restrict__ W,
        const float* __restrict__ bias, const float* __restrict__ res,
        float* __restrict__ C, __half* __restrict__ Ch,
        int M, int N, int K, float alpha, int epi) {
    __shared__ __align__(16) __half As[3 * 128 * GS];
    __shared__ __align__(16) __half Bs[3 * 64 * GS];
    gemm16_core(A, W, bias, res, C, Ch, M, N, K, alpha, epi, nullptr, nullptr, As, Bs);
}

__global__ __launch_bounds__(256) void qkv_gemm_kernel(
        const __half* __restrict__ HN, const __half* __restrict__ Wh,
        const float* __restrict__ bq, const float* __restrict__ bk,
        const float* __restrict__ bv,
        __half* __restrict__ QH, __half* __restrict__ KH,
        __half* __restrict__ VH,
        const float* __restrict__ sn, const float* __restrict__ cs) {
    __shared__ __align__(16) __half As[3 * 128 * GS];
    __shared__ __align__(16) __half Bs[3 * 64 * GS];
    int z = blockIdx.z;
    const __half* W = Wh + (z == 0 ? WH_WQ : z == 1 ? WH_WK : WH_WV);
    const float* bias = (z == 0) ? bq : (z == 1) ? bk : bv;
    __half* Ch = (z == 0) ? QH : (z == 1) ? KH : VH;
    float alpha = (z == 1) ? SCALING : 1.f;
    int epi = (z == 2) ? EPI_NONE : EPI_THETA;
    gemm16_core(HN, W, bias, nullptr, nullptr, Ch, Bb * L, E, E, alpha, epi, sn, cs, As, Bs);
}

__global__ __launch_bounds__(256) void ckv_gemm_kernel(
        const __half* __restrict__ XH, const __half* __restrict__ Wh,
        const float* __restrict__ ca_in_b,
        __half* __restrict__ CKH, __half* __restrict__ CVH) {
    __shared__ __align__(16) __half As[3 * 128 * GS];
    __shared__ __align__(16) __half Bs[3 * 64 * GS];
    int z = blockIdx.z;
    const __half* W = Wh + WH_CAIN + (size_t)(z + 1) * E * E;
    const float* bias = ca_in_b + (z + 1) * E;
    __half* Ch = z ? CVH : CKH;
    gemm16_core(XH, W, bias, nullptr, nullptr, Ch, Bb * L, E, E, 1.f, EPI_NONE,
                nullptr, nullptr, As, Bs);
}

// ---------------- fused dwconv3x3(+in) + LN1, interior fast path ---------
__global__ void dwconv3_ln_kernel(const float* __restrict__ in,
                                  const float* __restrict__ w,
                                  const float* __restrict__ bias,
                                  const float* __restrict__ g,
                                  const float* __restrict__ bln,
                                  float* __restrict__ X1,
                                  __half* __restrict__ HN) {
    int c = threadIdx.x;
    int wx = blockIdx.x, hy = blockIdx.y, b = blockIdx.z;
    float acc = bias[c];
    float wr[9];
#pragma unroll
    for (int i = 0; i < 9; i++) wr[i] = w[c * 9 + i];
    if (hy > 0 && hy < HH - 1 && wx > 0 && wx < WW - 1) {
        const float* p = in + (((size_t)b * HH + hy - 1) * WW + wx - 1) * E + c;
#pragma unroll
        for (int kh = 0; kh < 3; kh++)
#pragma unroll
            for (int kw = 0; kw < 3; kw++)
                acc += p[((size_t)kh * WW + kw) * E] * wr[kh * 3 + kw];
    } else {
#pragma unroll
        for (int kh = 0; kh < 3; kh++) {
            int y = hy + kh - 1;
            if (y < 0 || y >= HH) continue;
#pragma unroll
            for (int kw = 0; kw < 3; kw++) {
                int xx = wx + kw - 1;
                if (xx < 0 || xx >= WW) continue;
                acc += in[(((size_t)b * HH + y) * WW + xx) * E + c] *
                       wr[kh * 3 + kw];
            }
        }
    }
    size_t o = (((size_t)b * HH + hy) * WW + wx) * E + c;
    float v = in[o] + acc;
    X1[o] = v;
    __shared__ float red[2];
    blk_reduce2(v, v * v, red, c);
    float m = red[0] * (1.0f / E);
    float var = red[1] * (1.0f / E) - m * m;
    float inv = rsqrtf(var + 1e-6f);
    HN[o] = __float2half((v - m) * inv * g[c] + bln[c]);
}

// ---------------- dwconv 5x5: fp16 in, fp32 out, 4 px/thread -------------
__global__ __launch_bounds__(256) void dwconv5_kernel(
        const __half* __restrict__ VH, const float* __restrict__ w,
        const float* __restrict__ bias, float* __restrict__ out) {
    int c = threadIdx.x;
    int x0 = blockIdx.x * 4, hy = blockIdx.y, b = blockIdx.z;
    float wreg[25];
#pragma unroll
    for (int i = 0; i < 25; i++) wreg[i] = w[c * 25 + i];
    float bz = bias[c];
    float acc[4] = {bz, bz, bz, bz};
#pragma unroll
    for (int kh = 0; kh < 5; kh++) {
        int y = hy + kh - 2;
        if (y < 0 || y >= HH) continue;
        const __half* rbase = VH + (((size_t)b * HH + y) * WW) * E + c;
#pragma unroll
        for (int kw = 0; kw < 8; kw++) {
            int xx = x0 + kw - 2;
            if (xx < 0 || xx >= WW) continue;
            float v = __half2float(rbase[(size_t)xx * E]);
            int dx = kw - 2;
#pragma unroll
            for (int j = 0; j < 4; j++) {
                int kwi = dx - j + 2;
                if (kwi >= 0 && kwi < 5)
                    acc[j] += v * wreg[kh * 5 + kwi];
            }
        }
    }
    size_t obase = (((size_t)b * HH + hy) * WW + x0) * E + c;
#pragma unroll
    for (int j = 0; j < 4; j++)
        out[obase + (size_t)j * E] = acc[j];
}

// ---------------- AOH += LEPE -------------------------------------------
__global__ void add_lepe_kernel(__half* __restrict__ AOH,
                                const float* __restrict__ LEPE) {
    int idx = blockIdx.x * 256 + threadIdx.x;
    float v = __half2float(AOH[idx]) + LEPE[idx];
    AOH[idx] = __float2half(v);
}

// ---------------- layernorm: warp-per-row, no block sync -----------------
// 8 rows per 256-thread block; thread reduces 8 values (2x float4).
__global__ __launch_bounds__(256) void ln_kernel(
        const float* __restrict__ in, const float* __restrict__ g,
        const float* __restrict__ b, __half* __restrict__ out) {
    int warp = threadIdx.x >> 5, lane = threadIdx.x & 31;
    size_t row = (size_t)blockIdx.x * 8 + warp;
    const float* src = in + row * E;
    int c0 = lane * 4;
    float4 v0 = *(const float4*)&src[c0];
    float4 v1 = *(const float4*)&src[c0 + 128];
    float s = v0.x + v0.y + v0.z + v0.w + v1.x + v1.y + v1.z + v1.w;
    float q = v0.x * v0.x + v0.y * v0.y + v0.z * v0.z + v0.w * v0.w +
              v1.x * v1.x + v1.y * v1.y + v1.z * v1.z + v1.w * v1.w;
#pragma unroll
    for (int o = 16; o > 0; o >>= 1) {
        s += __shfl_xor_sync(0xffffffff, s, o);
        q += __shfl_xor_sync(0xffffffff, q, o);
    }
    float m = s * (1.0f / E);
    float var = q * (1.0f / E) - m * m;
    float inv = rsqrtf(var + 1e-6f);
    float4 g0 = *(const float4*)&g[c0];
    float4 g1 = *(const float4*)&g[c0 + 128];
    float4 b0 = *(const float4*)&b[c0];
    float4 b1 = *(const float4*)&b[c0 + 128];
    __half* dst = out + row * E;
    *(__half2*)&dst[c0] = __floats2half2_rn((v0.x - m) * inv * g0.x + b0.x,
                                            (v0.y - m) * inv * g0.y + b0.y);
    *(__half2*)&dst[c0 + 2] = __floats2half2_rn((v0.z - m) * inv * g0.z + b0.z,
                                                (v0.w - m) * inv * g0.w + b0.w);
    *(__half2*)&dst[c0 + 128] = __floats2half2_rn((v1.x - m) * inv * g1.x + b1.x,
                                                  (v1.y - m) * inv * g1.y + b1.y);
    *(__half2*)&dst[c0 + 130] = __floats2half2_rn((v1.z - m) * inv * g1.z + b1.z,
                                                  (v1.w - m) * inv * g1.w + b1.w);
}

// ---------------- fp16 flash attention, fixed-max softmax ----------------
#define KVS 40
#define PSS 72
__global__ __launch_bounds__(128) void attn_f16_kernel(
        const __half* __restrict__ Q, const __half* __restrict__ Kt,
        const __half* __restrict__ V,
        const float* __restrict__ mask,
        __half* __restrict__ O, float* __restrict__ PO, float* __restrict__ PL,
        int Lq, int Lk, float scale, int nsplit) {
    __shared__ __align__(16) __half Qs[64 * KVS];
    __shared__ __align__(16) __half Ks[3][64 * KVS];
    __shared__ __align__(16) __half Vs[3][64 * KVS];
    __shared__ __align__(16) __half Ps[64 * PSS];

    int tid = threadIdx.x;
    int w = tid >> 5, lane = tid & 31;
    int lg = lane >> 2, lt = lane & 3;
    int h = blockIdx.y, b = blockIdx.z;
    int qtiles = Lq >> 6;
    int split = blockIdx.x / qtiles;
    int q0 = (blockIdx.x - split * qtiles) * 64;
    int wm = w * 16;
    int ldrow = lane & 15;
    int ldcol = (lane >> 4) * 8;

    int NJ = (Lk >> 6) / nsplit;
    int jbase = split * NJ;

    auto loadTile = [&](__half* dst, const __half* src) {
#pragma unroll
        for (int i = 0; i < 2; i++) {
            int id = tid + 128 * i;
            int row = id >> 2, gr = id & 3;
            cp16(dst + row * KVS + gr * 8, src + (size_t)row * E + gr * 8);
        }
    };
    auto loadKV = [&](int s, int chunk) {
        loadTile(Ks[s], Kt + ((size_t)(b * Lk + (chunk << 6))) * E + h * KD);
        loadTile(Vs[s], V  + ((size_t)(b * Lk + (chunk << 6))) * E + h * KD);
        CP_COMMIT();
    };

    loadTile(Qs, Q + ((size_t)(b * Lq + q0)) * E + h * KD);
    CP_COMMIT();
    loadKV(0, jbase);
    if (NJ > 1) loadKV(1, jbase + 1);
    CP_WAIT(2);
    __syncthreads();

    uint32_t qf[2][4];
#pragma unroll
    for (int ks = 0; ks < 2; ks++)
        LDSM_X4(qf[ks][0], qf[ks][1], qf[ks][2], qf[ks][3],
                saddr(&Qs[(wm + ldrow) * KVS + ks * 16 + ldcol]));

    float ps0 = 0.f, ps1 = 0.f;
    float oacc[4][4] = {};
    const float* mbase = mask ? (mask + ((size_t)h * Lk + q0) * Lk) : nullptr;
    float sl2 = scale * LOG2E;

    for (int jt = 0; jt < NJ; jt++) {
        int j0 = (jbase + jt) << 6;
        if (jt + 1 < NJ) { CP_WAIT(1); } else { CP_WAIT(0); }
        __syncthreads();
        int s = jt % 3;

        float2 mv[8][2];
        if (mbase) {
            int r0 = wm + lg, r1 = wm + 8 + lg;
#pragma unroll
            for (int ni = 0; ni < 8; ni++) {
                int c = j0 + ni * 8 + lt * 2;
                mv[ni][0] = *(const float2*)&mbase[(size_t)r0 * Lk + c];
                mv[ni][1] = *(const float2*)&mbase[(size_t)r1 * Lk + c];
            }
        }

        float sacc[8][4];
#pragma unroll
        for (int ni = 0; ni < 8; ni++)
#pragma unroll
            for (int c = 0; c < 4; c++) sacc[ni][c] = 0.f;
#pragma unroll
        for (int ks = 0; ks < 2; ks++) {
#pragma unroll
            for (int nb = 0; nb < 4; nb++) {
                uint32_t r0, r1, r2, r3;
                LDSM_X4(r0, r1, r2, r3,
                        saddr(&Ks[s][(nb * 16 + ldrow) * KVS + ks * 16 + ldcol]));
                MMA_F16(sacc[2 * nb],     qf[ks][0], qf[ks][1], qf[ks][2], qf[ks][3], r0, r2);
                MMA_F16(sacc[2 * nb + 1], qf[ks][0], qf[ks][1], qf[ks][2], qf[ks][3], r1, r3);
            }
        }

#pragma unroll
        for (int ni = 0; ni < 8; ni++) {
            float p0, p1, p2, p3;
            if (mbase) {
                p0 = exp2f((sacc[ni][0] + mv[ni][0].x) * LOG2E);
                p1 = exp2f((sacc[ni][1] + mv[ni][0].y) * LOG2E);
                p2 = exp2f((sacc[ni][2] + mv[ni][1].x) * LOG2E);
                p3 = exp2f((sacc[ni][3] + mv[ni][1].y) * LOG2E);
            } else {
                p0 = exp2f(sacc[ni][0] * sl2);
                p1 = exp2f(sacc[ni][1] * sl2);
                p2 = exp2f(sacc[ni][2] * sl2);
                p3 = exp2f(sacc[ni][3] * sl2);
            }
            ps0 += p0 + p1;
            ps1 += p2 + p3;
            int c = ni * 8 + lt * 2;
            *(__half2*)&Ps[(wm + lg) * PSS + c]     = __floats2half2_rn(p0, p1);
            *(__half2*)&Ps[(wm + 8 + lg) * PSS + c] = __floats2half2_rn(p2, p3);
        }
        __syncwarp();

#pragma unroll
        for (int ks = 0; ks < 4; ks++) {
            uint32_t pa0, pa1, pa2, pa3;
            LDSM_X4(pa0, pa1, pa2, pa3,
                    saddr(&Ps[(wm + ldrow) * PSS + ks * 16 + ldcol]));
            uint32_t v0, v1, v2, v3;
            LDSM_X4T(v0, v1, v2, v3,
                     saddr(&Vs[s][(ks * 16 + ldrow) * KVS + 0 + ldcol]));
            uint32_t u0, u1, u2, u3;
            LDSM_X4T(u0, u1, u2, u3,
                     saddr(&Vs[s][(ks * 16 + ldrow) * KVS + 16 + ldcol]));
            MMA_F16(oacc[0], pa0, pa1, pa2, pa3, v0, v1);
            MMA_F16(oacc[1], pa0, pa1, pa2, pa3, v2, v3);
            MMA_F16(oacc[2], pa0, pa1, pa2, pa3, u0, u1);
            MMA_F16(oacc[3], pa0, pa1, pa2, pa3, u2, u3);
        }
        if (jt + 2 < NJ) loadKV((jt + 2) % 3, jbase + jt + 2);
    }

    ps0 += __shfl_xor_sync(0xffffffff, ps0, 1);
    ps0 += __shfl_xor_sync(0xffffffff, ps0, 2);
    ps1 += __shfl_xor_sync(0xffffffff, ps1, 1);
    ps1 += __shfl_xor_sync(0xffffffff, ps1, 2);

    int r0 = q0 + wm + lg, r1 = r0 + 8;
    if (nsplit == 1) {
        float inv0 = 1.f / ps0, inv1 = 1.f / ps1;
#pragma unroll
        for (int ni = 0; ni < 4; ni++) {
            int c = h * KD + ni * 8 + lt * 2;
            *(__half2*)&O[((size_t)(b * Lq + r0)) * E + c] =
                __floats2half2_rn(oacc[ni][0] * inv0, oacc[ni][1] * inv0);
            *(__half2*)&O[((size_t)(b * Lq + r1)) * E + c] =
                __floats2half2_rn(oacc[ni][2] * inv1, oacc[ni][3] * inv1);
        }
    } else {
        size_t base = (size_t)split * Bb * Lq;
#pragma unroll
        for (int ni = 0; ni < 4; ni++) {
            int c = h * KD + ni * 8 + lt * 2;
            *(float2*)&PO[(base + b * Lq + r0) * E + c] =
                make_float2(oacc[ni][0], oacc[ni][1]);
            *(float2*)&PO[(base + b * Lq + r1) * E + c] =
                make_float2(oacc[ni][2], oacc[ni][3]);
        }
        if (lt == 0) {
            size_t plb = (((size_t)split * Bb + b) * HEADS + h) * Lq;
            PL[plb + r0] = ps0;
            PL[plb + r1] = ps1;
        }
    }
}

// ---------------- split-KV reduce ----------------------------------------
__global__ void attn_reduce_kernel(const float* __restrict__ PO,
                                   const float* __restrict__ PL,
                                   __half* __restrict__ out) {
    int idx = blockIdx.x * 256 + threadIdx.x;
    int e = idx & (E - 1);
    int bq = idx >> 8;
    int q = bq & (NQ - 1);
    int b = bq >> 6;
    int h = e >> 5;
    float num = 0.f, den = 0.f;
#pragma unroll
    for (int s = 0; s < NSPLIT; s++) {
        num += PO[((size_t)s * Bb * NQ + bq) * E + e];
        den += PL[(((size_t)s * Bb + b) * HEADS + h) * NQ + q];
    }
    out[idx] = __float2half(num / den);
}

// ---------------- launcher ----------------------------------------------
extern "C" void kernel_launch(void* const* d_in, const int* in_sizes, int n_in,
                              void* d_out, int out_size) {
    const float* x       = (const float*)d_in[0];
    const float* queries = (const float*)d_in[1];
    const float* sn      = (const float*)d_in[2];
    const float* cs      = (const float*)d_in[3];
    const float* mask    = (const float*)d_in[4];
    const float* ln1_g   = (const float*)d_in[5];
    const float* ln1_b   = (const float*)d_in[6];
    const float* ln2_g   = (const float*)d_in[7];
    const float* ln2_b   = (const float*)d_in[8];
    const float* wq      = (const float*)d_in[9];
    const float* bq      = (const float*)d_in[10];
    const float* wk      = (const float*)d_in[11];
    const float* bk      = (const float*)d_in[12];
    const float* wv      = (const float*)d_in[13];
    const float* bv      = (const float*)d_in[14];
    const float* lepe_w  = (const float*)d_in[15];
    const float* lepe_b  = (const float*)d_in[16];
    const float* wo      = (const float*)d_in[17];
    const float* bo      = (const float*)d_in[18];
    const float* fc1_w   = (const float*)d_in[19];
    const float* fc1_b   = (const float*)d_in[20];
    const float* fc2_w   = (const float*)d_in[21];
    const float* fc2_b   = (const float*)d_in[22];
    const float* pos_w   = (const float*)d_in[23];
    const float* pos_b   = (const float*)d_in[24];
    const float* ca_in_w = (const float*)d_in[25];
    const float* ca_in_b = (const float*)d_in[26];
    const float* ca_out_w= (const float*)d_in[27];
    const float* ca_out_b= (const float*)d_in[28];

    void* sp = nullptr;
    cudaGetSymbolAddress(&sp, g_scratch);
    float* S = (float*)sp;
    float* X1   = S + OFF_X1;
    float* LEPE = S + OFF_LEPE;
    float* X2   = S + OFF_X2;
    float* Q2   = S + OFF_Q2;
    float* PO   = S + OFF_PO;
    float* PL   = S + OFF_PL;
    __half* HN   = (__half*)(S + OFF_HN);
    __half* QH   = (__half*)(S + OFF_QH);
    __half* KH   = (__half*)(S + OFF_KH);
    __half* VH   = (__half*)(S + OFF_VH);
    __half* AOH  = (__half*)(S + OFF_AOH);
    __half* XH   = (__half*)(S + OFF_XH);
    __half* CKH  = (__half*)(S + OFF_CKH);
    __half* CVH  = (__half*)(S + OFF_CVH);
    __half* FF   = (__half*)(S + OFF_FF);
    __half* CQH  = (__half*)(S + OFF_CQH);
    __half* CAOH = (__half*)(S + OFF_CAOH);
    __half* QLN  = (__half*)(S + OFF_QLN);
    __half* QLN2 = (__half*)(S + OFF_QLN2);
    __half* QFF  = (__half*)(S + OFF_QFF);
    __half* WHb  = (__half*)(S + OFF_WH);

    float* OX = (float*)d_out;
    float* OQ = OX + (size_t)Bb * L * E;

    const int MTOK = Bb * L;   // 8192
    const int MQ   = Bb * NQ;  // 512
    dim3 sp3(WW, HH, Bb);
    dim3 c5(WW / 4, HH, Bb);

    static cudaStream_t s2 = nullptr, s3 = nullptr;
    static cudaEvent_t ev0 = nullptr, evW = nullptr, evQ = nullptr,
                       evV = nullptr, evL = nullptr;
    if (!s2) {
        cudaStreamCreateWithFlags(&s2, cudaStreamNonBlocking);
        cudaStreamCreateWithFlags(&s3, cudaStreamNonBlocking);
        cudaEventCreateWithFlags(&ev0, cudaEventDisableTiming);
        cudaEventCreateWithFlags(&evW, cudaEventDisableTiming);
        cudaEventCreateWithFlags(&evQ, cudaEventDisableTiming);
        cudaEventCreateWithFlags(&evV, cudaEventDisableTiming);
        cudaEventCreateWithFlags(&evL, cudaEventDisableTiming);
    }

    // fork side stream s2: weights conversion + queries prologue
    cudaEventRecord(ev0, 0);
    cudaStreamWaitEvent(s2, ev0, 0);
    wconv_kernel<<<dim3(128, 8), 256, 0, s2>>>(wq, wk, wv, wo, fc1_w, fc2_w,
                                               ca_in_w, ca_out_w, WHb);
    cudaEventRecord(evW, s2);
    ln_kernel<<<MQ / 8, 256, 0, s2>>>(queries, ln1_g, ln1_b, QLN);
    gemm_kernel<<<dim3(E/64, MQ/128), 256, 0, s2>>>(
        QLN, WHb + WH_CAIN, ca_in_b, nullptr, nullptr, CQH, MQ, E, E, 1.f, EPI_NONE);
    cudaEventRecord(evQ, s2);

    // main: dwconv3 + LN1 (independent of weights)
    dwconv3_ln_kernel<<<sp3, 256>>>(x, pos_w, pos_b, ln1_g, ln1_b, X1, HN);
    cudaStreamWaitEvent(0, evW, 0);
    qkv_gemm_kernel<<<dim3(E/64, MTOK/128, 3), 256>>>(
        HN, WHb, bq, bk, bv, QH, KH, VH, sn, cs);
    cudaEventRecord(evV, 0);

    // fork s3: dwconv5 runs concurrently with self-attention
    cudaStreamWaitEvent(s3, evV, 0);
    dwconv5_kernel<<<c5, 256, 0, s3>>>(VH, lepe_w, lepe_b, LEPE);
    cudaEventRecord(evL, s3);

    // self attention
    attn_f16_kernel<<<dim3(L/64, HEADS, Bb), 128>>>(
        QH, KH, VH, mask, AOH, nullptr, nullptr, L, L, 1.f, 1);
    cudaStreamWaitEvent(0, evL, 0);
    add_lepe_kernel<<<(Bb * L * E) / 256, 256>>>(AOH, LEPE);

    // x2 = x1 + aoh @ wo^T + bo
    gemm_kernel<<<dim3(E/64, MTOK/128), 256>>>(AOH, WHb + WH_WO, bo, X1, X2, nullptr, MTOK, E, E, 1.f, EPI_NONE);
    // FFN on x
    ln_kernel<<<MTOK / 8, 256>>>(X2, ln2_g, ln2_b, HN);
    gemm_kernel<<<dim3(FFN/64, MTOK/128), 256>>>(HN, WHb + WH_FC1, fc1_b, nullptr, nullptr, FF, MTOK, FFN, E, 1.f, EPI_GELU);
    gemm_kernel<<<dim3(E/64, MTOK/128), 256>>>(FF, WHb + WH_FC2, fc2_b, X2, OX, XH, MTOK, E, FFN, 1.f, EPI_NONE);
    // cross attention (split-KV); CQH from s2
    ckv_gemm_kernel<<<dim3(E/64, MTOK/128, 2), 256>>>(XH, WHb, ca_in_b, CKH, CVH);
    cudaStreamWaitEvent(0, evQ, 0);
    attn_f16_kernel<<<dim3(NSPLIT, HEADS, Bb), 128>>>(
        CQH, CKH, CVH, nullptr, nullptr, PO, PL, NQ, L, SCALING, NSPLIT);
    attn_reduce_kernel<<<(Bb * NQ * E) / 256, 256>>>(PO, PL, CAOH);
    gemm_kernel<<<dim3(E/64, MQ/128), 256>>>(CAOH, WHb + WH_CAOUT, ca_out_b, queries, Q2, nullptr, MQ, E, E, 1.f, EPI_NONE);
    // FFN on queries
    ln_kernel<<<MQ / 8, 256>>>(Q2, ln2_g, ln2_b, QLN2);
    gemm_kernel<<<dim3(FFN/64, MQ/128), 256>>>(QLN2, WHb + WH_FC1, fc1_b, nullptr, nullptr, QFF, MQ, FFN, E, 1.f, EPI_GELU);
    gemm_kernel<<<dim3(E/64, MQ/128), 256>>>(QFF, WHb + WH_FC2, fc2_b, Q2, OQ, nullptr, MQ, E, FFN, 1.f, EPI_NONE);
}

// round 16
// speedup vs baseline: 1.0878x; 1.0311x over previous
#include <cuda_runtime.h>
#include <cuda_fp16.h>
#include <math.h>
#include <stdint.h>

#define Bb 8
#define HH 32
#define WW 32
#define E 256
#define HEADS 8
#define KD 32
#define FFN 1024
#define NQ 64
#define L 1024
#define SCALING 0.17677669529663687f
#define LOG2E 1.4426950408889634f
#define NSPLIT 8

#define EPI_NONE 0
#define EPI_GELU 1
#define EPI_THETA 2

// ---------------- scratch arena (float units) ----------------
#define SZ_TOK ((size_t)Bb * L * E)
#define SZ_QTK ((size_t)Bb * NQ * E)
#define OFF_X1    ((size_t)0)
#define OFF_LEPE  (OFF_X1 + SZ_TOK)
#define OFF_X2    (OFF_LEPE + SZ_TOK)
#define OFF_Q2    (OFF_X2 + SZ_TOK)
#define OFF_HN    (OFF_Q2 + SZ_QTK)
#define OFF_QH    (OFF_HN + SZ_TOK / 2)
#define OFF_KH    (OFF_QH + SZ_TOK / 2)
#define OFF_VH    (OFF_KH + SZ_TOK / 2)
#define OFF_AOH   (OFF_VH + SZ_TOK / 2)
#define OFF_XH    (OFF_AOH + SZ_TOK / 2)
#define OFF_CKH   (OFF_XH + SZ_TOK / 2)
#define OFF_CVH   (OFF_CKH + SZ_TOK / 2)
#define OFF_FF    (OFF_CVH + SZ_TOK / 2)
#define OFF_CQH   (OFF_FF + (size_t)Bb * L * FFN / 2)
#define OFF_CAOH  (OFF_CQH + SZ_QTK / 2)
#define OFF_QLN   (OFF_CAOH + SZ_QTK / 2)
#define OFF_QLN2  (OFF_QLN + SZ_QTK / 2)
#define OFF_QFF   (OFF_QLN2 + SZ_QTK / 2)
#define OFF_WH    (OFF_QFF + (size_t)Bb * NQ * FFN / 2)
#define OFF_PO    (OFF_WH + 524288)
#define OFF_PL    (OFF_PO + (size_t)NSPLIT * SZ_QTK)
#define SCRATCH_TOTAL (OFF_PL + (size_t)NSPLIT * Bb * HEADS * NQ)

__device__ float g_scratch[SCRATCH_TOTAL];

// fp16 weight arena offsets (half units)
#define WH_WQ    0
#define WH_WK    65536
#define WH_WV    131072
#define WH_WO    196608
#define WH_FC1   262144
#define WH_FC2   524288
#define WH_CAIN  786432
#define WH_CAOUT 983040

// ---------------- helpers ----------------
__device__ __forceinline__ void cp16(void* dst, const void* src) {
    uint32_t d = (uint32_t)__cvta_generic_to_shared(dst);
    asm volatile("cp.async.cg.shared.global [%0], [%1], 16;" :: "r"(d), "l"(src));
}
#define CP_COMMIT() asm volatile("cp.async.commit_group;" ::: "memory")
#define CP_WAIT(N)  asm volatile("cp.async.wait_group %0;" :: "n"(N) : "memory")

__device__ __forceinline__ uint32_t saddr(const void* p) {
    return (uint32_t)__cvta_generic_to_shared(p);
}

#define LDSM_X4(r0, r1, r2, r3, a)                                          \
    asm volatile("ldmatrix.sync.aligned.m8n8.x4.shared.b16 {%0,%1,%2,%3}, [%4];" \
        : "=r"(r0), "=r"(r1), "=r"(r2), "=r"(r3) : "r"(a))
#define LDSM_X4T(r0, r1, r2, r3, a)                                         \
    asm volatile("ldmatrix.sync.aligned.m8n8.x4.trans.shared.b16 {%0,%1,%2,%3}, [%4];" \
        : "=r"(r0), "=r"(r1), "=r"(r2), "=r"(r3) : "r"(a))

#define MMA_F16(acc, a0, a1, a2, a3, b0, b1)                                \
    asm volatile(                                                           \
        "mma.sync.aligned.m16n8k16.row.col.f32.f16.f16.f32 "                \
        "{%0,%1,%2,%3}, {%4,%5,%6,%7}, {%8,%9}, {%0,%1,%2,%3};"             \
        : "+f"(acc[0]), "+f"(acc[1]), "+f"(acc[2]), "+f"(acc[3])            \
        : "r"(a0), "r"(a1), "r"(a2), "r"(a3), "r"(b0), "r"(b1))

// ---------------- weight fp32 -> fp16 conversion ----------------
__global__ void wconv_kernel(const float* __restrict__ wq, const float* __restrict__ wk,
                             const float* __restrict__ wv, const float* __restrict__ wo,
                             const float* __restrict__ fc1, const float* __restrict__ fc2,
                             const float* __restrict__ cain, const float* __restrict__ caout,
                             __half* __restrict__ Wh) {
    const int sizes[8] = {65536, 65536, 65536, 65536, 262144, 262144, 196608, 65536};
    const int offs[8]  = {WH_WQ, WH_WK, WH_WV, WH_WO, WH_FC1, WH_FC2, WH_CAIN, WH_CAOUT};
    int z = blockIdx.y;
    const float* src = z == 0 ? wq : z == 1 ? wk : z == 2 ? wv : z == 3 ? wo
                     : z == 4 ? fc1 : z == 5 ? fc2 : z == 6 ? cain : caout;
    int n = sizes[z];
    __half* dst = Wh + offs[z];
    for (int i = blockIdx.x * 256 + threadIdx.x; i < n; i += gridDim.x * 256)
        dst[i] = __float2half(src[i]);
}

// ---------------- fp16 GEMM core (3-stage pipeline, 128x64 tile) ---------
#define GS 40
__device__ __forceinline__ void gemm16_core(
        const __half* __restrict__ A, const __half* __restrict__ W,
        const float* __restrict__ bias, const float* __restrict__ res,
        float* __restrict__ C, __half* __restrict__ Ch,
        int M, int N, int K, float alpha, int epi,
        const float* __restrict__ sn, const float* __restrict__ cs,
        __half* As, __half* Bs) {
    int tid = threadIdx.x;
    int w = tid >> 5, lane = tid & 31;
    int wm = (w & 3) * 32, wn = (w >> 2) * 32;
    int m0 = blockIdx.y * 128, n0 = blockIdx.x * 64;
    int lg = lane >> 2, lt = lane & 3;
    int ldrow = lane & 15;
    int ldcol = (lane >> 4) * 8;

    float acc[2][4][4] = {};

    auto loadTile = [&](int s, int k0) {
        __half* Ab = As + s * 128 * GS;
        __half* Bd = Bs + s * 64 * GS;
#pragma unroll
        for (int i = 0; i < 2; i++) {
            int id = tid + 256 * i;
            int row = id >> 2, f = id & 3;
            cp16(&Ab[row * GS + f * 8], &A[(size_t)(m0 + row) * K + k0 + f * 8]);
        }
        {
            int row = tid >> 2, f = tid & 3;
            cp16(&Bd[row * GS + f * 8], &W[(size_t)(n0 + row) * K + k0 + f * 8]);
        }
    };

    int KT = K >> 5;
    loadTile(0, 0);
    CP_COMMIT();
    if (KT > 1) { loadTile(1, 32); CP_COMMIT(); }
    for (int kt = 0; kt < KT; kt++) {
        if (kt + 1 < KT) { CP_WAIT(1); } else { CP_WAIT(0); }
        __syncthreads();
        int s = kt % 3;
        const __half* Ab = As + s * 128 * GS;
        const __half* Bd = Bs + s * 64 * GS;
#pragma unroll
        for (int ks = 0; ks < 2; ks++) {
            uint32_t af[2][4];
#pragma unroll
            for (int mi = 0; mi < 2; mi++)
                LDSM_X4(af[mi][0], af[mi][1], af[mi][2], af[mi][3],
                        saddr(&Ab[(wm + mi * 16 + ldrow) * GS + ks * 16 + ldcol]));
#pragma unroll
            for (int nb = 0; nb < 2; nb++) {
                uint32_t b0, b1, b2, b3;
                LDSM_X4(b0, b1, b2, b3,
                        saddr(&Bd[(wn + nb * 16 + ldrow) * GS + ks * 16 + ldcol]));
#pragma unroll
                for (int mi = 0; mi < 2; mi++) {
                    MMA_F16(acc[mi][nb * 2],     af[mi][0], af[mi][1], af[mi][2], af[mi][3], b0, b2);
                    MMA_F16(acc[mi][nb * 2 + 1], af[mi][0], af[mi][1], af[mi][2], af[mi][3], b1, b3);
                }
            }
        }
        if (kt + 2 < KT) { loadTile((kt + 2) % 3, (kt + 2) << 5); CP_COMMIT(); }
    }

    // epilogue
#pragma unroll
    for (int mi = 0; mi < 2; mi++) {
#pragma unroll
        for (int ni = 0; ni < 4; ni++) {
            int r = m0 + wm + mi * 16 + lg;
            int c = n0 + wn + ni * 8 + lt * 2;
            float b0 = bias[c], b1 = bias[c + 1];
#pragma unroll
            for (int half_ = 0; half_ < 2; half_++) {
                int rr = r + half_ * 8;
                float v0 = (acc[mi][ni][half_ * 2 + 0] + b0) * alpha;
                float v1 = (acc[mi][ni][half_ * 2 + 1] + b1) * alpha;
                if (epi == EPI_GELU) {
                    v0 = 0.5f * v0 * (1.0f + erff(v0 * 0.70710678118654752f));
                    v1 = 0.5f * v1 * (1.0f + erff(v1 * 0.70710678118654752f));
                } else if (epi == EPI_THETA) {
                    int l = rr & (L - 1);
                    int d0 = c & 31;
                    const float* sp = sn + l * KD + d0;
                    const float* cq = cs + l * KD + d0;
                    float s0 = sp[0], s1 = sp[1];
                    float c0 = cq[0], c1 = cq[1];
                    float o0 = v0 * c0 - v1 * s0;
                    float o1 = v1 * c1 + v0 * s1;
                    v0 = o0; v1 = o1;
                }
                if (res) {
                    v0 += res[(size_t)rr * N + c];
                    v1 += res[(size_t)rr * N + c + 1];
                }
                if (C)
                    *(float2*)&C[(size_t)rr * N + c] = make_float2(v0, v1);
                if (Ch)
                    *(__half2*)&Ch[(size_t)rr * N + c] = __floats2half2_rn(v0, v1);
            }
        }
    }
}

__global__ __launch_bounds__(256) void gemm_kernel(
        const __half* __restrict__ A, const __half* __restrict__ W,
        const float* __restrict__ bias, const float* __restrict__ res,
        float* __restrict__ C, __half* __restrict__ Ch,
        int M, int N, int K, float alpha, int epi) {
    __shared__ __align__(16) __half As[3 * 128 * GS];
    __shared__ __align__(16) __half Bs[3 * 64 * GS];
    gemm16_core(A, W, bias, res, C, Ch, M, N, K, alpha, epi, nullptr, nullptr, As, Bs);
}

__global__ __launch_bounds__(256) void qkv_gemm_kernel(
        const __half* __restrict__ HN, const __half* __restrict__ Wh,
        const float* __restrict__ bq, const float* __restrict__ bk,
        const float* __restrict__ bv,
        __half* __restrict__ QH, __half* __restrict__ KH,
        __half* __restrict__ VH,
        const float* __restrict__ sn, const float* __restrict__ cs) {
    __shared__ __align__(16) __half As[3 * 128 * GS];
    __shared__ __align__(16) __half Bs[3 * 64 * GS];
    int z = blockIdx.z;
    const __half* W = Wh + (z == 0 ? WH_WQ : z == 1 ? WH_WK : WH_WV);
    const float* bias = (z == 0) ? bq : (z == 1) ? bk : bv;
    __half* Ch = (z == 0) ? QH : (z == 1) ? KH : VH;
    float alpha = (z == 1) ? SCALING : 1.f;
    int epi = (z == 2) ? EPI_NONE : EPI_THETA;
    gemm16_core(HN, W, bias, nullptr, nullptr, Ch, Bb * L, E, E, alpha, epi, sn, cs, As, Bs);
}

__global__ __launch_bounds__(256) void ckv_gemm_kernel(
        const __half* __restrict__ XH, const __half* __restrict__ Wh,
        const float* __restrict__ ca_in_b,
        __half* __restrict__ CKH, __half* __restrict__ CVH) {
    __shared__ __align__(16) __half As[3 * 128 * GS];
    __shared__ __align__(16) __half Bs[3 * 64 * GS];
    int z = blockIdx.z;
    const __half* W = Wh + WH_CAIN + (size_t)(z + 1) * E * E;
    const float* bias = ca_in_b + (z + 1) * E;
    __half* Ch = z ? CVH : CKH;
    gemm16_core(XH, W, bias, nullptr, nullptr, Ch, Bb * L, E, E, 1.f, EPI_NONE,
                nullptr, nullptr, As, Bs);
}

// ---------------- fused dwconv3x3(+in) + LN1: warp-per-pixel -------------
// 8 pixels per 256-thread block. Lane owns channels c0=lane*4 and c0+128.
// Weights staged in smem as [tap][channel] for coalesced float4 reads.
__global__ __launch_bounds__(256) void dwconv3_ln_kernel(
        const float* __restrict__ in, const float* __restrict__ w,
        const float* __restrict__ bias, const float* __restrict__ g,
        const float* __restrict__ bln,
        float* __restrict__ X1, __half* __restrict__ HN) {
    __shared__ float ws[9][E];
    int tid = threadIdx.x;
    // stage transposed weights: ws[tap][c] = w[c*9+tap]
    for (int i = tid; i < 9 * E; i += 256) {
        int c = i >> 3;              // not exact split; do full loop
    }
    // simpler exact staging: each thread covers 9 entries of one channel
    {
        int c = tid;
#pragma unroll
        for (int t = 0; t < 9; t++) ws[t][c] = w[c * 9 + t];
    }
    __syncthreads();

    int warp = tid >> 5, lane = tid & 31;
    int p = blockIdx.x * 8 + warp;           // pixel index over Bb*HH*WW
    int b = p >> 10;
    int rem = p & 1023;
    int hy = rem >> 5, wx = rem & 31;
    int c0 = lane * 4;

    float4 a0 = make_float4(0.f, 0.f, 0.f, 0.f);
    float4 a1 = a0;
    bool interior = (hy > 0 && hy < HH - 1 && wx > 0 && wx < WW - 1);
    const float* base = in + (((size_t)b * HH + hy) * WW + wx) * E;

#pragma unroll
    for (int kh = 0; kh < 3; kh++) {
        int y = hy + kh - 1;
        if (!interior && (y < 0 || y >= HH)) continue;
#pragma unroll
        for (int kw = 0; kw < 3; kw++) {
            int xx = wx + kw - 1;
            if (!interior && (xx < 0 || xx >= WW)) continue;
            const float* pp = in + (((size_t)b * HH + y) * WW + xx) * E;
            float4 v0 = *(const float4*)&pp[c0];
            float4 v1 = *(const float4*)&pp[c0 + 128];
            int t = kh * 3 + kw;
            float4 w0 = *(const float4*)&ws[t][c0];
            float4 w1 = *(const float4*)&ws[t][c0 + 128];
            a0.x += v0.x * w0.x; a0.y += v0.y * w0.y;
            a0.z += v0.z * w0.z; a0.w += v0.w * w0.w;
            a1.x += v1.x * w1.x; a1.y += v1.y * w1.y;
            a1.z += v1.z * w1.z; a1.w += v1.w * w1.w;
        }
    }

    float4 x0 = *(const float4*)&base[c0];
    float4 x1 = *(const float4*)&base[c0 + 128];
    float4 bb0 = *(const float4*)&bias[c0];
    float4 bb1 = *(const float4*)&bias[c0 + 128];
    float4 v0, v1;
    v0.x = x0.x + a0.x + bb0.x; v0.y = x0.y + a0.y + bb0.y;
    v0.z = x0.z + a0.z + bb0.z; v0.w = x0.w + a0.w + bb0.w;
    v1.x = x1.x + a1.x + bb1.x; v1.y = x1.y + a1.y + bb1.y;
    v1.z = x1.z + a1.z + bb1.z; v1.w = x1.w + a1.w + bb1.w;

    float* xo = X1 + (((size_t)b * HH + hy) * WW + wx) * E;
    *(float4*)&xo[c0] = v0;
    *(float4*)&xo[c0 + 128] = v1;

    float s = v0.x + v0.y + v0.z + v0.w + v1.x + v1.y + v1.z + v1.w;
    float q = v0.x * v0.x + v0.y * v0.y + v0.z * v0.z + v0.w * v0.w +
              v1.x * v1.x + v1.y * v1.y + v1.z * v1.z + v1.w * v1.w;
#pragma unroll
    for (int o = 16; o > 0; o >>= 1) {
        s += __shfl_xor_sync(0xffffffff, s, o);
        q += __shfl_xor_sync(0xffffffff, q, o);
    }
    float m = s * (1.0f / E);
    float var = q * (1.0f / E) - m * m;
    float inv = rsqrtf(var + 1e-6f);
    float4 g0 = *(const float4*)&g[c0];
    float4 g1 = *(const float4*)&g[c0 + 128];
    float4 l0 = *(const float4*)&bln[c0];
    float4 l1 = *(const float4*)&bln[c0 + 128];
    __half* hn = HN + (((size_t)b * HH + hy) * WW + wx) * E;
    *(__half2*)&hn[c0]       = __floats2half2_rn((v0.x - m) * inv * g0.x + l0.x,
                                                 (v0.y - m) * inv * g0.y + l0.y);
    *(__half2*)&hn[c0 + 2]   = __floats2half2_rn((v0.z - m) * inv * g0.z + l0.z,
                                                 (v0.w - m) * inv * g0.w + l0.w);
    *(__half2*)&hn[c0 + 128] = __floats2half2_rn((v1.x - m) * inv * g1.x + l1.x,
                                                 (v1.y - m) * inv * g1.y + l1.y);
    *(__half2*)&hn[c0 + 130] = __floats2half2_rn((v1.z - m) * inv * g1.z + l1.z,
                                                 (v1.w - m) * inv * g1.w + l1.w);
}

// ---------------- dwconv 5x5: fp16 in, fp32 out, 4 px/thread -------------
__global__ __launch_bounds__(256) void dwconv5_kernel(
        const __half* __restrict__ VH, const float* __restrict__ w,
        const float* __restrict__ bias, float* __restrict__ out) {
    int c = threadIdx.x;
    int x0 = blockIdx.x * 4, hy = blockIdx.y, b = blockIdx.z;
    float wreg[25];
#pragma unroll
    for (int i = 0; i < 25; i++) wreg[i] = w[c * 25 + i];
    float bz = bias[c];
    float acc[4] = {bz, bz, bz, bz};
#pragma unroll
    for (int kh = 0; kh < 5; kh++) {
        int y = hy + kh - 2;
        if (y < 0 || y >= HH) continue;
        const __half* rbase = VH + (((size_t)b * HH + y) * WW) * E + c;
#pragma unroll
        for (int kw = 0; kw < 8; kw++) {
            int xx = x0 + kw - 2;
            if (xx < 0 || xx >= WW) continue;
            float v = __half2float(rbase[(size_t)xx * E]);
            int dx = kw - 2;
#pragma unroll
            for (int j = 0; j < 4; j++) {
                int kwi = dx - j + 2;
                if (kwi >= 0 && kwi < 5)
                    acc[j] += v * wreg[kh * 5 + kwi];
            }
        }
    }
    size_t obase = (((size_t)b * HH + hy) * WW + x0) * E + c;
#pragma unroll
    for (int j = 0; j < 4; j++)
        out[obase + (size_t)j * E] = acc[j];
}

// ---------------- AOH += LEPE -------------------------------------------
__global__ void add_lepe_kernel(__half* __restrict__ AOH,
                                const float* __restrict__ LEPE) {
    int idx = blockIdx.x * 256 + threadIdx.x;
    float v = __half2float(AOH[idx]) + LEPE[idx];
    AOH[idx] = __float2half(v);
}

// ---------------- layernorm: warp-per-row ---------------------------------
__global__ __launch_bounds__(256) void ln_kernel(
        const float* __restrict__ in, const float* __restrict__ g,
        const float* __restrict__ b, __half* __restrict__ out) {
    int warp = threadIdx.x >> 5, lane = threadIdx.x & 31;
    size_t row = (size_t)blockIdx.x * 8 + warp;
    const float* src = in + row * E;
    int c0 = lane * 4;
    float4 v0 = *(const float4*)&src[c0];
    float4 v1 = *(const float4*)&src[c0 + 128];
    float s = v0.x + v0.y + v0.z + v0.w + v1.x + v1.y + v1.z + v1.w;
    float q = v0.x * v0.x + v0.y * v0.y + v0.z * v0.z + v0.w * v0.w +
              v1.x * v1.x + v1.y * v1.y + v1.z * v1.z + v1.w * v1.w;
#pragma unroll
    for (int o = 16; o > 0; o >>= 1) {
        s += __shfl_xor_sync(0xffffffff, s, o);
        q += __shfl_xor_sync(0xffffffff, q, o);
    }
    float m = s * (1.0f / E);
    float var = q * (1.0f / E) - m * m;
    float inv = rsqrtf(var + 1e-6f);
    float4 g0 = *(const float4*)&g[c0];
    float4 g1 = *(const float4*)&g[c0 + 128];
    float4 b0 = *(const float4*)&b[c0];
    float4 b1 = *(const float4*)&b[c0 + 128];
    __half* dst = out + row * E;
    *(__half2*)&dst[c0] = __floats2half2_rn((v0.x - m) * inv * g0.x + b0.x,
                                            (v0.y - m) * inv * g0.y + b0.y);
    *(__half2*)&dst[c0 + 2] = __floats2half2_rn((v0.z - m) * inv * g0.z + b0.z,
                                                (v0.w - m) * inv * g0.w + b0.w);
    *(__half2*)&dst[c0 + 128] = __floats2half2_rn((v1.x - m) * inv * g1.x + b1.x,
                                                  (v1.y - m) * inv * g1.y + b1.y);
    *(__half2*)&dst[c0 + 130] = __floats2half2_rn((v1.z - m) * inv * g1.z + b1.z,
                                                  (v1.w - m) * inv * g1.w + b1.w);
}

// ---------------- fp16 flash attention, fixed-max softmax ----------------
#define KVS 40
#define PSS 72
__global__ __launch_bounds__(128) void attn_f16_kernel(
        const __half* __restrict__ Q, const __half* __restrict__ Kt,
        const __half* __restrict__ V,
        const float* __restrict__ mask,
        __half* __restrict__ O, float* __restrict__ PO, float* __restrict__ PL,
        int Lq, int Lk, float scale, int nsplit) {
    __shared__ __align__(16) __half Qs[64 * KVS];
    __shared__ __align__(16) __half Ks[3][64 * KVS];
    __shared__ __align__(16) __half Vs[3][64 * KVS];
    __shared__ __align__(16) __half Ps[64 * PSS];

    int tid = threadIdx.x;
    int w = tid >> 5, lane = tid & 31;
    int lg = lane >> 2, lt = lane & 3;
    int h = blockIdx.y, b = blockIdx.z;
    int qtiles = Lq >> 6;
    int split = blockIdx.x / qtiles;
    int q0 = (blockIdx.x - split * qtiles) * 64;
    int wm = w * 16;
    int ldrow = lane & 15;
    int ldcol = (lane >> 4) * 8;

    int NJ = (Lk >> 6) / nsplit;
    int jbase = split * NJ;

    auto loadTile = [&](__half* dst, const __half* src) {
#pragma unroll
        for (int i = 0; i < 2; i++) {
            int id = tid + 128 * i;
            int row = id >> 2, gr = id & 3;
            cp16(dst + row * KVS + gr * 8, src + (size_t)row * E + gr * 8);
        }
    };
    auto loadKV = [&](int s, int chunk) {
        loadTile(Ks[s], Kt + ((size_t)(b * Lk + (chunk << 6))) * E + h * KD);
        loadTile(Vs[s], V  + ((size_t)(b * Lk + (chunk << 6))) * E + h * KD);
        CP_COMMIT();
    };

    loadTile(Qs, Q + ((size_t)(b * Lq + q0)) * E + h * KD);
    CP_COMMIT();
    loadKV(0, jbase);
    if (NJ > 1) loadKV(1, jbase + 1);
    CP_WAIT(2);
    __syncthreads();

    uint32_t qf[2][4];
#pragma unroll
    for (int ks = 0; ks < 2; ks++)
        LDSM_X4(qf[ks][0], qf[ks][1], qf[ks][2], qf[ks][3],
                saddr(&Qs[(wm + ldrow) * KVS + ks * 16 + ldcol]));

    float ps0 = 0.f, ps1 = 0.f;
    float oacc[4][4] = {};
    const float* mbase = mask ? (mask + ((size_t)h * Lk + q0) * Lk) : nullptr;
    float sl2 = scale * LOG2E;

    for (int jt = 0; jt < NJ; jt++) {
        int j0 = (jbase + jt) << 6;
        if (jt + 1 < NJ) { CP_WAIT(1); } else { CP_WAIT(0); }
        __syncthreads();
        int s = jt % 3;

        float2 mv[8][2];
        if (mbase) {
            int r0 = wm + lg, r1 = wm + 8 + lg;
#pragma unroll
            for (int ni = 0; ni < 8; ni++) {
                int c = j0 + ni * 8 + lt * 2;
                mv[ni][0] = *(const float2*)&mbase[(size_t)r0 * Lk + c];
                mv[ni][1] = *(const float2*)&mbase[(size_t)r1 * Lk + c];
            }
        }

        float sacc[8][4];
#pragma unroll
        for (int ni = 0; ni < 8; ni++)
#pragma unroll
            for (int c = 0; c < 4; c++) sacc[ni][c] = 0.f;
#pragma unroll
        for (int ks = 0; ks < 2; ks++) {
#pragma unroll
            for (int nb = 0; nb < 4; nb++) {
                uint32_t r0, r1, r2, r3;
                LDSM_X4(r0, r1, r2, r3,
                        saddr(&Ks[s][(nb * 16 + ldrow) * KVS + ks * 16 + ldcol]));
                MMA_F16(sacc[2 * nb],     qf[ks][0], qf[ks][1], qf[ks][2], qf[ks][3], r0, r2);
                MMA_F16(sacc[2 * nb + 1], qf[ks][0], qf[ks][1], qf[ks][2], qf[ks][3], r1, r3);
            }
        }

#pragma unroll
        for (int ni = 0; ni < 8; ni++) {
            float p0, p1, p2, p3;
            if (mbase) {
                p0 = exp2f((sacc[ni][0] + mv[ni][0].x) * LOG2E);
                p1 = exp2f((sacc[ni][1] + mv[ni][0].y) * LOG2E);
                p2 = exp2f((sacc[ni][2] + mv[ni][1].x) * LOG2E);
                p3 = exp2f((sacc[ni][3] + mv[ni][1].y) * LOG2E);
            } else {
                p0 = exp2f(sacc[ni][0] * sl2);
                p1 = exp2f(sacc[ni][1] * sl2);
                p2 = exp2f(sacc[ni][2] * sl2);
                p3 = exp2f(sacc[ni][3] * sl2);
            }
            ps0 += p0 + p1;
            ps1 += p2 + p3;
            int c = ni * 8 + lt * 2;
            *(__half2*)&Ps[(wm + lg) * PSS + c]     = __floats2half2_rn(p0, p1);
            *(__half2*)&Ps[(wm + 8 + lg) * PSS + c] = __floats2half2_rn(p2, p3);
        }
        __syncwarp();

#pragma unroll
        for (int ks = 0; ks < 4; ks++) {
            uint32_t pa0, pa1, pa2, pa3;
            LDSM_X4(pa0, pa1, pa2, pa3,
                    saddr(&Ps[(wm + ldrow) * PSS + ks * 16 + ldcol]));
            uint32_t v0, v1, v2, v3;
            LDSM_X4T(v0, v1, v2, v3,
                     saddr(&Vs[s][(ks * 16 + ldrow) * KVS + 0 + ldcol]));
            uint32_t u0, u1, u2, u3;
            LDSM_X4T(u0, u1, u2, u3,
                     saddr(&Vs[s][(ks * 16 + ldrow) * KVS + 16 + ldcol]));
            MMA_F16(oacc[0], pa0, pa1, pa2, pa3, v0, v1);
            MMA_F16(oacc[1], pa0, pa1, pa2, pa3, v2, v3);
            MMA_F16(oacc[2], pa0, pa1, pa2, pa3, u0, u1);
            MMA_F16(oacc[3], pa0, pa1, pa2, pa3, u2, u3);
        }
        if (jt + 2 < NJ) loadKV((jt + 2) % 3, jbase + jt + 2);
    }

    ps0 += __shfl_xor_sync(0xffffffff, ps0, 1);
    ps0 += __shfl_xor_sync(0xffffffff, ps0, 2);
    ps1 += __shfl_xor_sync(0xffffffff, ps1, 1);
    ps1 += __shfl_xor_sync(0xffffffff, ps1, 2);

    int r0 = q0 + wm + lg, r1 = r0 + 8;
    if (nsplit == 1) {
        float inv0 = 1.f / ps0, inv1 = 1.f / ps1;
#pragma unroll
        for (int ni = 0; ni < 4; ni++) {
            int c = h * KD + ni * 8 + lt * 2;
            *(__half2*)&O[((size_t)(b * Lq + r0)) * E + c] =
                __floats2half2_rn(oacc[ni][0] * inv0, oacc[ni][1] * inv0);
            *(__half2*)&O[((size_t)(b * Lq + r1)) * E + c] =
                __floats2half2_rn(oacc[ni][2] * inv1, oacc[ni][3] * inv1);
        }
    } else {
        size_t base = (size_t)split * Bb * Lq;
#pragma unroll
        for (int ni = 0; ni < 4; ni++) {
            int c = h * KD + ni * 8 + lt * 2;
            *(float2*)&PO[(base + b * Lq + r0) * E + c] =
                make_float2(oacc[ni][0], oacc[ni][1]);
            *(float2*)&PO[(base + b * Lq + r1) * E + c] =
                make_float2(oacc[ni][2], oacc[ni][3]);
        }
        if (lt == 0) {
            size_t plb = (((size_t)split * Bb + b) * HEADS + h) * Lq;
            PL[plb + r0] = ps0;
            PL[plb + r1] = ps1;
        }
    }
}

// ---------------- split-KV reduce ----------------------------------------
__global__ void attn_reduce_kernel(const float* __restrict__ PO,
                                   const float* __restrict__ PL,
                                   __half* __restrict__ out) {
    int idx = blockIdx.x * 256 + threadIdx.x;
    int e = idx & (E - 1);
    int bq = idx >> 8;
    int q = bq & (NQ - 1);
    int b = bq >> 6;
    int h = e >> 5;
    float num = 0.f, den = 0.f;
#pragma unroll
    for (int s = 0; s < NSPLIT; s++) {
        num += PO[((size_t)s * Bb * NQ + bq) * E + e];
        den += PL[(((size_t)s * Bb + b) * HEADS + h) * NQ + q];
    }
    out[idx] = __float2half(num / den);
}

// ---------------- launcher ----------------------------------------------
extern "C" void kernel_launch(void* const* d_in, const int* in_sizes, int n_in,
                              void* d_out, int out_size) {
    const float* x       = (const float*)d_in[0];
    const float* queries = (const float*)d_in[1];
    const float* sn      = (const float*)d_in[2];
    const float* cs      = (const float*)d_in[3];
    const float* mask    = (const float*)d_in[4];
    const float* ln1_g   = (const float*)d_in[5];
    const float* ln1_b   = (const float*)d_in[6];
    const float* ln2_g   = (const float*)d_in[7];
    const float* ln2_b   = (const float*)d_in[8];
    const float* wq      = (const float*)d_in[9];
    const float* bq      = (const float*)d_in[10];
    const float* wk      = (const float*)d_in[11];
    const float* bk      = (const float*)d_in[12];
    const float* wv      = (const float*)d_in[13];
    const float* bv      = (const float*)d_in[14];
    const float* lepe_w  = (const float*)d_in[15];
    const float* lepe_b  = (const float*)d_in[16];
    const float* wo      = (const float*)d_in[17];
    const float* bo      = (const float*)d_in[18];
    const float* fc1_w   = (const float*)d_in[19];
    const float* fc1_b   = (const float*)d_in[20];
    const float* fc2_w   = (const float*)d_in[21];
    const float* fc2_b   = (const float*)d_in[22];
    const float* pos_w   = (const float*)d_in[23];
    const float* pos_b   = (const float*)d_in[24];
    const float* ca_in_w = (const float*)d_in[25];
    const float* ca_in_b = (const float*)d_in[26];
    const float* ca_out_w= (const float*)d_in[27];
    const float* ca_out_b= (const float*)d_in[28];

    void* sp = nullptr;
    cudaGetSymbolAddress(&sp, g_scratch);
    float* S = (float*)sp;
    float* X1   = S + OFF_X1;
    float* LEPE = S + OFF_LEPE;
    float* X2   = S + OFF_X2;
    float* Q2   = S + OFF_Q2;
    float* PO   = S + OFF_PO;
    float* PL   = S + OFF_PL;
    __half* HN   = (__half*)(S + OFF_HN);
    __half* QH   = (__half*)(S + OFF_QH);
    __half* KH   = (__half*)(S + OFF_KH);
    __half* VH   = (__half*)(S + OFF_VH);
    __half* AOH  = (__half*)(S + OFF_AOH);
    __half* XH   = (__half*)(S + OFF_XH);
    __half* CKH  = (__half*)(S + OFF_CKH);
    __half* CVH  = (__half*)(S + OFF_CVH);
    __half* FF   = (__half*)(S + OFF_FF);
    __half* CQH  = (__half*)(S + OFF_CQH);
    __half* CAOH = (__half*)(S + OFF_CAOH);
    __half* QLN  = (__half*)(S + OFF_QLN);
    __half* QLN2 = (__half*)(S + OFF_QLN2);
    __half* QFF  = (__half*)(S + OFF_QFF);
    __half* WHb  = (__half*)(S + OFF_WH);

    float* OX = (float*)d_out;
    float* OQ = OX + (size_t)Bb * L * E;

    const int MTOK = Bb * L;   // 8192
    const int MQ   = Bb * NQ;  // 512
    dim3 c5(WW / 4, HH, Bb);

    static cudaStream_t s2 = nullptr, s3 = nullptr;
    static cudaEvent_t ev0 = nullptr, evW = nullptr, evQ = nullptr,
                       evV = nullptr, evL = nullptr;
    if (!s2) {
        cudaStreamCreateWithFlags(&s2, cudaStreamNonBlocking);
        cudaStreamCreateWithFlags(&s3, cudaStreamNonBlocking);
        cudaEventCreateWithFlags(&ev0, cudaEventDisableTiming);
        cudaEventCreateWithFlags(&evW, cudaEventDisableTiming);
        cudaEventCreateWithFlags(&evQ, cudaEventDisableTiming);
        cudaEventCreateWithFlags(&evV, cudaEventDisableTiming);
        cudaEventCreateWithFlags(&evL, cudaEventDisableTiming);
    }

    // fork s2: weights + queries prologue
    cudaEventRecord(ev0, 0);
    cudaStreamWaitEvent(s2, ev0, 0);
    wconv_kernel<<<dim3(128, 8), 256, 0, s2>>>(wq, wk, wv, wo, fc1_w, fc2_w,
                                               ca_in_w, ca_out_w, WHb);
    cudaEventRecord(evW, s2);
    ln_kernel<<<MQ / 8, 256, 0, s2>>>(queries, ln1_g, ln1_b, QLN);
    gemm_kernel<<<dim3(E/64, MQ/128), 256, 0, s2>>>(
        QLN, WHb + WH_CAIN, ca_in_b, nullptr, nullptr, CQH, MQ, E, E, 1.f, EPI_NONE);
    cudaEventRecord(evQ, s2);

    // main: dwconv3 + LN1 (warp-per-pixel)
    dwconv3_ln_kernel<<<(Bb * HH * WW) / 8, 256>>>(x, pos_w, pos_b, ln1_g, ln1_b, X1, HN);
    cudaStreamWaitEvent(0, evW, 0);
    qkv_gemm_kernel<<<dim3(E/64, MTOK/128, 3), 256>>>(
        HN, WHb, bq, bk, bv, QH, KH, VH, sn, cs);
    cudaEventRecord(evV, 0);

    // fork s3: dwconv5 concurrent with self-attention
    cudaStreamWaitEvent(s3, evV, 0);
    dwconv5_kernel<<<c5, 256, 0, s3>>>(VH, lepe_w, lepe_b, LEPE);
    cudaEventRecord(evL, s3);

    attn_f16_kernel<<<dim3(L/64, HEADS, Bb), 128>>>(
        QH, KH, VH, mask, AOH, nullptr, nullptr, L, L, 1.f, 1);
    cudaStreamWaitEvent(0, evL, 0);
    add_lepe_kernel<<<(Bb * L * E) / 256, 256>>>(AOH, LEPE);

    gemm_kernel<<<dim3(E/64, MTOK/128), 256>>>(AOH, WHb + WH_WO, bo, X1, X2, nullptr, MTOK, E, E, 1.f, EPI_NONE);
    ln_kernel<<<MTOK / 8, 256>>>(X2, ln2_g, ln2_b, HN);
    gemm_kernel<<<dim3(FFN/64, MTOK/128), 256>>>(HN, WHb + WH_FC1, fc1_b, nullptr, nullptr, FF, MTOK, FFN, E, 1.f, EPI_GELU);
    gemm_kernel<<<dim3(E/64, MTOK/128), 256>>>(FF, WHb + WH_FC2, fc2_b, X2, OX, XH, MTOK, E, FFN, 1.f, EPI_NONE);
    ckv_gemm_kernel<<<dim3(E/64, MTOK/128, 2), 256>>>(XH, WHb, ca_in_b, CKH, CVH);
    cudaStreamWaitEvent(0, evQ, 0);
    attn_f16_kernel<<<dim3(NSPLIT, HEADS, Bb), 128>>>(
        CQH, CKH, CVH, nullptr, nullptr, PO, PL, NQ, L, SCALING, NSPLIT);
    attn_reduce_kernel<<<(Bb * NQ * E) / 256, 256>>>(PO, PL, CAOH);
    gemm_kernel<<<dim3(E/64, MQ/128), 256>>>(CAOH, WHb + WH_CAOUT, ca_out_b, queries, Q2, nullptr, MQ, E, E, 1.f, EPI_NONE);
    ln_kernel<<<MQ / 8, 256>>>(Q2, ln2_g, ln2_b, QLN2);
    gemm_kernel<<<dim3(FFN/64, MQ/128), 256>>>(QLN2, WHb + WH_FC1, fc1_b, nullptr, nullptr, QFF, MQ, FFN, E, 1.f, EPI_GELU);
    gemm_kernel<<<dim3(E/64, MQ/128), 256>>>(QFF, WHb + WH_FC2, fc2_b, Q2, OQ, nullptr, MQ, E, FFN, 1.f, EPI_NONE);
}

// round 17
// speedup vs baseline: 1.1180x; 1.0278x over previous
#include <cuda_runtime.h>
#include <cuda_fp16.h>
#include <math.h>
#include <stdint.h>

#define Bb 8
#define HH 32
#define WW 32
#define E 256
#define HEADS 8
#define KD 32
#define FFN 1024
#define NQ 64
#define L 1024
#define SCALING 0.17677669529663687f
#define LOG2E 1.4426950408889634f
#define NSPLIT 8

#define EPI_NONE 0
#define EPI_GELU 1
#define EPI_THETA 2

// ---------------- scratch arena (float units) ----------------
#define SZ_TOK ((size_t)Bb * L * E)
#define SZ_QTK ((size_t)Bb * NQ * E)
#define OFF_X1    ((size_t)0)
#define OFF_LEPE  (OFF_X1 + SZ_TOK)
#define OFF_X2    (OFF_LEPE + SZ_TOK)
#define OFF_Q2    (OFF_X2 + SZ_TOK)
#define OFF_HN    (OFF_Q2 + SZ_QTK)
#define OFF_QH    (OFF_HN + SZ_TOK / 2)
#define OFF_KH    (OFF_QH + SZ_TOK / 2)
#define OFF_VH    (OFF_KH + SZ_TOK / 2)
#define OFF_AOH   (OFF_VH + SZ_TOK / 2)
#define OFF_XH    (OFF_AOH + SZ_TOK / 2)
#define OFF_CKH   (OFF_XH + SZ_TOK / 2)
#define OFF_CVH   (OFF_CKH + SZ_TOK / 2)
#define OFF_FF    (OFF_CVH + SZ_TOK / 2)
#define OFF_CQH   (OFF_FF + (size_t)Bb * L * FFN / 2)
#define OFF_CAOH  (OFF_CQH + SZ_QTK / 2)
#define OFF_QLN   (OFF_CAOH + SZ_QTK / 2)
#define OFF_QLN2  (OFF_QLN + SZ_QTK / 2)
#define OFF_QFF   (OFF_QLN2 + SZ_QTK / 2)
#define OFF_WH    (OFF_QFF + (size_t)Bb * NQ * FFN / 2)
#define OFF_PO    (OFF_WH + 524288)
#define OFF_PL    (OFF_PO + (size_t)NSPLIT * SZ_QTK)
#define SCRATCH_TOTAL (OFF_PL + (size_t)NSPLIT * Bb * HEADS * NQ)

__device__ float g_scratch[SCRATCH_TOTAL];

// fp16 weight arena offsets (half units)
#define WH_WQ    0
#define WH_WK    65536
#define WH_WV    131072
#define WH_WO    196608
#define WH_FC1   262144
#define WH_FC2   524288
#define WH_CAIN  786432
#define WH_CAOUT 983040

// ---------------- helpers ----------------
__device__ __forceinline__ void cp16(void* dst, const void* src) {
    uint32_t d = (uint32_t)__cvta_generic_to_shared(dst);
    asm volatile("cp.async.cg.shared.global [%0], [%1], 16;" :: "r"(d), "l"(src));
}
#define CP_COMMIT() asm volatile("cp.async.commit_group;" ::: "memory")
#define CP_WAIT(N)  asm volatile("cp.async.wait_group %0;" :: "n"(N) : "memory")

__device__ __forceinline__ uint32_t saddr(const void* p) {
    return (uint32_t)__cvta_generic_to_shared(p);
}

#define LDSM_X4(r0, r1, r2, r3, a)                                          \
    asm volatile("ldmatrix.sync.aligned.m8n8.x4.shared.b16 {%0,%1,%2,%3}, [%4];" \
        : "=r"(r0), "=r"(r1), "=r"(r2), "=r"(r3) : "r"(a))
#define LDSM_X4T(r0, r1, r2, r3, a)                                         \
    asm volatile("ldmatrix.sync.aligned.m8n8.x4.trans.shared.b16 {%0,%1,%2,%3}, [%4];" \
        : "=r"(r0), "=r"(r1), "=r"(r2), "=r"(r3) : "r"(a))

#define MMA_F16(acc, a0, a1, a2, a3, b0, b1)                                \
    asm volatile(                                                           \
        "mma.sync.aligned.m16n8k16.row.col.f32.f16.f16.f32 "                \
        "{%0,%1,%2,%3}, {%4,%5,%6,%7}, {%8,%9}, {%0,%1,%2,%3};"             \
        : "+f"(acc[0]), "+f"(acc[1]), "+f"(acc[2]), "+f"(acc[3])            \
        : "r"(a0), "r"(a1), "r"(a2), "r"(a3), "r"(b0), "r"(b1))

// ---------------- weight fp32 -> fp16 conversion ----------------
__global__ void wconv_kernel(const float* __restrict__ wq, const float* __restrict__ wk,
                             const float* __restrict__ wv, const float* __restrict__ wo,
                             const float* __restrict__ fc1, const float* __restrict__ fc2,
                             const float* __restrict__ cain, const float* __restrict__ caout,
                             __half* __restrict__ Wh) {
    const int sizes[8] = {65536, 65536, 65536, 65536, 262144, 262144, 196608, 65536};
    const int offs[8]  = {WH_WQ, WH_WK, WH_WV, WH_WO, WH_FC1, WH_FC2, WH_CAIN, WH_CAOUT};
    int z = blockIdx.y;
    const float* src = z == 0 ? wq : z == 1 ? wk : z == 2 ? wv : z == 3 ? wo
                     : z == 4 ? fc1 : z == 5 ? fc2 : z == 6 ? cain : caout;
    int n = sizes[z];
    __half* dst = Wh + offs[z];
    for (int i = blockIdx.x * 256 + threadIdx.x; i < n; i += gridDim.x * 256)
        dst[i] = __float2half(src[i]);
}

// ---------------- fp16 GEMM core (3-stage pipeline, 128x64 tile, k64) ----
#define GS 72
#define GSMB (3 * (128 + 64) * GS * 2)
__device__ __forceinline__ void gemm16_core(
        const __half* __restrict__ A, const __half* __restrict__ W,
        const float* __restrict__ bias, const float* __restrict__ res,
        float* __restrict__ C, __half* __restrict__ Ch,
        int M, int N, int K, float alpha, int epi,
        const float* __restrict__ sn, const float* __restrict__ cs,
        __half* As, __half* Bs) {
    int tid = threadIdx.x;
    int w = tid >> 5, lane = tid & 31;
    int wm = (w & 3) * 32, wn = (w >> 2) * 32;
    int m0 = blockIdx.y * 128, n0 = blockIdx.x * 64;
    int lg = lane >> 2, lt = lane & 3;
    int ldrow = lane & 15;
    int ldcol = (lane >> 4) * 8;

    float acc[2][4][4] = {};

    auto loadTile = [&](int s, int k0) {
        __half* Ab = As + s * 128 * GS;
        __half* Bd = Bs + s * 64 * GS;
#pragma unroll
        for (int i = 0; i < 4; i++) {
            int id = tid + 256 * i;
            int row = id >> 3, f = id & 7;
            cp16(&Ab[row * GS + f * 8], &A[(size_t)(m0 + row) * K + k0 + f * 8]);
        }
#pragma unroll
        for (int i = 0; i < 2; i++) {
            int id = tid + 256 * i;
            int row = id >> 3, f = id & 7;
            cp16(&Bd[row * GS + f * 8], &W[(size_t)(n0 + row) * K + k0 + f * 8]);
        }
        CP_COMMIT();
    };

    int KT = K >> 6;
    loadTile(0, 0);
    if (KT > 1) loadTile(1, 64);
    for (int kt = 0; kt < KT; kt++) {
        if (kt + 1 < KT) { CP_WAIT(1); } else { CP_WAIT(0); }
        __syncthreads();
        int s = kt % 3;
        const __half* Ab = As + s * 128 * GS;
        const __half* Bd = Bs + s * 64 * GS;
#pragma unroll
        for (int ks = 0; ks < 4; ks++) {
            uint32_t af[2][4];
#pragma unroll
            for (int mi = 0; mi < 2; mi++)
                LDSM_X4(af[mi][0], af[mi][1], af[mi][2], af[mi][3],
                        saddr(&Ab[(wm + mi * 16 + ldrow) * GS + ks * 16 + ldcol]));
#pragma unroll
            for (int nb = 0; nb < 2; nb++) {
                uint32_t b0, b1, b2, b3;
                LDSM_X4(b0, b1, b2, b3,
                        saddr(&Bd[(wn + nb * 16 + ldrow) * GS + ks * 16 + ldcol]));
#pragma unroll
                for (int mi = 0; mi < 2; mi++) {
                    MMA_F16(acc[mi][nb * 2],     af[mi][0], af[mi][1], af[mi][2], af[mi][3], b0, b2);
                    MMA_F16(acc[mi][nb * 2 + 1], af[mi][0], af[mi][1], af[mi][2], af[mi][3], b1, b3);
                }
            }
        }
        if (kt + 2 < KT) loadTile((kt + 2) % 3, (kt + 2) << 6);
    }

    // epilogue
#pragma unroll
    for (int mi = 0; mi < 2; mi++) {
#pragma unroll
        for (int ni = 0; ni < 4; ni++) {
            int r = m0 + wm + mi * 16 + lg;
            int c = n0 + wn + ni * 8 + lt * 2;
            float b0 = bias[c], b1 = bias[c + 1];
#pragma unroll
            for (int half_ = 0; half_ < 2; half_++) {
                int rr = r + half_ * 8;
                float v0 = (acc[mi][ni][half_ * 2 + 0] + b0) * alpha;
                float v1 = (acc[mi][ni][half_ * 2 + 1] + b1) * alpha;
                if (epi == EPI_GELU) {
                    v0 = 0.5f * v0 * (1.0f + erff(v0 * 0.70710678118654752f));
                    v1 = 0.5f * v1 * (1.0f + erff(v1 * 0.70710678118654752f));
                } else if (epi == EPI_THETA) {
                    int l = rr & (L - 1);
                    int d0 = c & 31;
                    const float* sp = sn + l * KD + d0;
                    const float* cq = cs + l * KD + d0;
                    float s0 = sp[0], s1 = sp[1];
                    float c0 = cq[0], c1 = cq[1];
                    float o0 = v0 * c0 - v1 * s0;
                    float o1 = v1 * c1 + v0 * s1;
                    v0 = o0; v1 = o1;
                }
                if (res) {
                    v0 += res[(size_t)rr * N + c];
                    v1 += res[(size_t)rr * N + c + 1];
                }
                if (C)
                    *(float2*)&C[(size_t)rr * N + c] = make_float2(v0, v1);
                if (Ch)
                    *(__half2*)&Ch[(size_t)rr * N + c] = __floats2half2_rn(v0, v1);
            }
        }
    }
}

__global__ __launch_bounds__(256) void gemm_kernel(
        const __half* __restrict__ A, const __half* __restrict__ W,
        const float* __restrict__ bias, const float* __restrict__ res,
        float* __restrict__ C, __half* __restrict__ Ch,
        int M, int N, int K, float alpha, int epi) {
    extern __shared__ __half gsm[];
    gemm16_core(A, W, bias, res, C, Ch, M, N, K, alpha, epi, nullptr, nullptr,
                gsm, gsm + 3 * 128 * GS);
}

__global__ __launch_bounds__(256) void qkv_gemm_kernel(
        const __half* __restrict__ HN, const __half* __restrict__ Wh,
        const float* __restrict__ bq, const float* __restrict__ bk,
        const float* __restrict__ bv,
        __half* __restrict__ QH, __half* __restrict__ KH,
        __half* __restrict__ VH,
        const float* __restrict__ sn, const float* __restrict__ cs) {
    extern __shared__ __half gsm[];
    int z = blockIdx.z;
    const __half* W = Wh + (z == 0 ? WH_WQ : z == 1 ? WH_WK : WH_WV);
    const float* bias = (z == 0) ? bq : (z == 1) ? bk : bv;
    __half* Ch = (z == 0) ? QH : (z == 1) ? KH : VH;
    float alpha = (z == 1) ? SCALING : 1.f;
    int epi = (z == 2) ? EPI_NONE : EPI_THETA;
    gemm16_core(HN, W, bias, nullptr, nullptr, Ch, Bb * L, E, E, alpha, epi, sn, cs,
                gsm, gsm + 3 * 128 * GS);
}

__global__ __launch_bounds__(256) void ckv_gemm_kernel(
        const __half* __restrict__ XH, const __half* __restrict__ Wh,
        const float* __restrict__ ca_in_b,
        __half* __restrict__ CKH, __half* __restrict__ CVH) {
    extern __shared__ __half gsm[];
    int z = blockIdx.z;
    const __half* W = Wh + WH_CAIN + (size_t)(z + 1) * E * E;
    const float* bias = ca_in_b + (z + 1) * E;
    __half* Ch = z ? CVH : CKH;
    gemm16_core(XH, W, bias, nullptr, nullptr, Ch, Bb * L, E, E, 1.f, EPI_NONE,
                nullptr, nullptr, gsm, gsm + 3 * 128 * GS);
}

// ---------------- fused dwconv3x3(+in) + LN1: warp-per-pixel -------------
__global__ __launch_bounds__(256) void dwconv3_ln_kernel(
        const float* __restrict__ in, const float* __restrict__ w,
        const float* __restrict__ bias, const float* __restrict__ g,
        const float* __restrict__ bln,
        float* __restrict__ X1, __half* __restrict__ HN) {
    __shared__ float ws[9][E];
    int tid = threadIdx.x;
    {
        int c = tid;
#pragma unroll
        for (int t = 0; t < 9; t++) ws[t][c] = w[c * 9 + t];
    }
    __syncthreads();

    int warp = tid >> 5, lane = tid & 31;
    int p = blockIdx.x * 8 + warp;
    int b = p >> 10;
    int rem = p & 1023;
    int hy = rem >> 5, wx = rem & 31;
    int c0 = lane * 4;

    float4 a0 = make_float4(0.f, 0.f, 0.f, 0.f);
    float4 a1 = a0;
    bool interior = (hy > 0 && hy < HH - 1 && wx > 0 && wx < WW - 1);
    const float* base = in + (((size_t)b * HH + hy) * WW + wx) * E;

#pragma unroll
    for (int kh = 0; kh < 3; kh++) {
        int y = hy + kh - 1;
        if (!interior && (y < 0 || y >= HH)) continue;
#pragma unroll
        for (int kw = 0; kw < 3; kw++) {
            int xx = wx + kw - 1;
            if (!interior && (xx < 0 || xx >= WW)) continue;
            const float* pp = in + (((size_t)b * HH + y) * WW + xx) * E;
            float4 v0 = *(const float4*)&pp[c0];
            float4 v1 = *(const float4*)&pp[c0 + 128];
            int t = kh * 3 + kw;
            float4 w0 = *(const float4*)&ws[t][c0];
            float4 w1 = *(const float4*)&ws[t][c0 + 128];
            a0.x += v0.x * w0.x; a0.y += v0.y * w0.y;
            a0.z += v0.z * w0.z; a0.w += v0.w * w0.w;
            a1.x += v1.x * w1.x; a1.y += v1.y * w1.y;
            a1.z += v1.z * w1.z; a1.w += v1.w * w1.w;
        }
    }

    float4 x0 = *(const float4*)&base[c0];
    float4 x1 = *(const float4*)&base[c0 + 128];
    float4 bb0 = *(const float4*)&bias[c0];
    float4 bb1 = *(const float4*)&bias[c0 + 128];
    float4 v0, v1;
    v0.x = x0.x + a0.x + bb0.x; v0.y = x0.y + a0.y + bb0.y;
    v0.z = x0.z + a0.z + bb0.z; v0.w = x0.w + a0.w + bb0.w;
    v1.x = x1.x + a1.x + bb1.x; v1.y = x1.y + a1.y + bb1.y;
    v1.z = x1.z + a1.z + bb1.z; v1.w = x1.w + a1.w + bb1.w;

    float* xo = X1 + (((size_t)b * HH + hy) * WW + wx) * E;
    *(float4*)&xo[c0] = v0;
    *(float4*)&xo[c0 + 128] = v1;

    float s = v0.x + v0.y + v0.z + v0.w + v1.x + v1.y + v1.z + v1.w;
    float q = v0.x * v0.x + v0.y * v0.y + v0.z * v0.z + v0.w * v0.w +
              v1.x * v1.x + v1.y * v1.y + v1.z * v1.z + v1.w * v1.w;
#pragma unroll
    for (int o = 16; o > 0; o >>= 1) {
        s += __shfl_xor_sync(0xffffffff, s, o);
        q += __shfl_xor_sync(0xffffffff, q, o);
    }
    float m = s * (1.0f / E);
    float var = q * (1.0f / E) - m * m;
    float inv = rsqrtf(var + 1e-6f);
    float4 g0 = *(const float4*)&g[c0];
    float4 g1 = *(const float4*)&g[c0 + 128];
    float4 l0 = *(const float4*)&bln[c0];
    float4 l1 = *(const float4*)&bln[c0 + 128];
    __half* hn = HN + (((size_t)b * HH + hy) * WW + wx) * E;
    *(__half2*)&hn[c0]       = __floats2half2_rn((v0.x - m) * inv * g0.x + l0.x,
                                                 (v0.y - m) * inv * g0.y + l0.y);
    *(__half2*)&hn[c0 + 2]   = __floats2half2_rn((v0.z - m) * inv * g0.z + l0.z,
                                                 (v0.w - m) * inv * g0.w + l0.w);
    *(__half2*)&hn[c0 + 128] = __floats2half2_rn((v1.x - m) * inv * g1.x + l1.x,
                                                 (v1.y - m) * inv * g1.y + l1.y);
    *(__half2*)&hn[c0 + 130] = __floats2half2_rn((v1.z - m) * inv * g1.z + l1.z,
                                                 (v1.w - m) * inv * g1.w + l1.w);
}

// ---------------- dwconv 5x5: fp16 in, fp32 out, 4 px/thread -------------
__global__ __launch_bounds__(256) void dwconv5_kernel(
        const __half* __restrict__ VH, const float* __restrict__ w,
        const float* __restrict__ bias, float* __restrict__ out) {
    int c = threadIdx.x;
    int x0 = blockIdx.x * 4, hy = blockIdx.y, b = blockIdx.z;
    float wreg[25];
#pragma unroll
    for (int i = 0; i < 25; i++) wreg[i] = w[c * 25 + i];
    float bz = bias[c];
    float acc[4] = {bz, bz, bz, bz};
#pragma unroll
    for (int kh = 0; kh < 5; kh++) {
        int y = hy + kh - 2;
        if (y < 0 || y >= HH) continue;
        const __half* rbase = VH + (((size_t)b * HH + y) * WW) * E + c;
#pragma unroll
        for (int kw = 0; kw < 8; kw++) {
            int xx = x0 + kw - 2;
            if (xx < 0 || xx >= WW) continue;
            float v = __half2float(rbase[(size_t)xx * E]);
            int dx = kw - 2;
#pragma unroll
            for (int j = 0; j < 4; j++) {
                int kwi = dx - j + 2;
                if (kwi >= 0 && kwi < 5)
                    acc[j] += v * wreg[kh * 5 + kwi];
            }
        }
    }
    size_t obase = (((size_t)b * HH + hy) * WW + x0) * E + c;
#pragma unroll
    for (int j = 0; j < 4; j++)
        out[obase + (size_t)j * E] = acc[j];
}

// ---------------- AOH += LEPE (vectorized) -------------------------------
__global__ void add_lepe_kernel(__half* __restrict__ AOH,
                                const float* __restrict__ LEPE) {
    int idx = (blockIdx.x * 256 + threadIdx.x) * 4;
    __half2 h0 = *(__half2*)&AOH[idx];
    __half2 h1 = *(__half2*)&AOH[idx + 2];
    float4 lv = *(const float4*)&LEPE[idx];
    float2 f0 = __half22float2(h0);
    float2 f1 = __half22float2(h1);
    *(__half2*)&AOH[idx]     = __floats2half2_rn(f0.x + lv.x, f0.y + lv.y);
    *(__half2*)&AOH[idx + 2] = __floats2half2_rn(f1.x + lv.z, f1.y + lv.w);
}

// ---------------- layernorm: warp-per-row ---------------------------------
__global__ __launch_bounds__(256) void ln_kernel(
        const float* __restrict__ in, const float* __restrict__ g,
        const float* __restrict__ b, __half* __restrict__ out) {
    int warp = threadIdx.x >> 5, lane = threadIdx.x & 31;
    size_t row = (size_t)blockIdx.x * 8 + warp;
    const float* src = in + row * E;
    int c0 = lane * 4;
    float4 v0 = *(const float4*)&src[c0];
    float4 v1 = *(const float4*)&src[c0 + 128];
    float s = v0.x + v0.y + v0.z + v0.w + v1.x + v1.y + v1.z + v1.w;
    float q = v0.x * v0.x + v0.y * v0.y + v0.z * v0.z + v0.w * v0.w +
              v1.x * v1.x + v1.y * v1.y + v1.z * v1.z + v1.w * v1.w;
#pragma unroll
    for (int o = 16; o > 0; o >>= 1) {
        s += __shfl_xor_sync(0xffffffff, s, o);
        q += __shfl_xor_sync(0xffffffff, q, o);
    }
    float m = s * (1.0f / E);
    float var = q * (1.0f / E) - m * m;
    float inv = rsqrtf(var + 1e-6f);
    float4 g0 = *(const float4*)&g[c0];
    float4 g1 = *(const float4*)&g[c0 + 128];
    float4 b0 = *(const float4*)&b[c0];
    float4 b1 = *(const float4*)&b[c0 + 128];
    __half* dst = out + row * E;
    *(__half2*)&dst[c0] = __floats2half2_rn((v0.x - m) * inv * g0.x + b0.x,
                                            (v0.y - m) * inv * g0.y + b0.y);
    *(__half2*)&dst[c0 + 2] = __floats2half2_rn((v0.z - m) * inv * g0.z + b0.z,
                                                (v0.w - m) * inv * g0.w + b0.w);
    *(__half2*)&dst[c0 + 128] = __floats2half2_rn((v1.x - m) * inv * g1.x + b1.x,
                                                  (v1.y - m) * inv * g1.y + b1.y);
    *(__half2*)&dst[c0 + 130] = __floats2half2_rn((v1.z - m) * inv * g1.z + b1.z,
                                                  (v1.w - m) * inv * g1.w + b1.w);
}

// ---------------- fp16 flash attention, fixed-max softmax ----------------
#define KVS 40
#define PSS 72
__global__ __launch_bounds__(128) void attn_f16_kernel(
        const __half* __restrict__ Q, const __half* __restrict__ Kt,
        const __half* __restrict__ V,
        const float* __restrict__ mask,
        __half* __restrict__ O, float* __restrict__ PO, float* __restrict__ PL,
        int Lq, int Lk, float scale, int nsplit) {
    __shared__ __align__(16) __half Qs[64 * KVS];
    __shared__ __align__(16) __half Ks[3][64 * KVS];
    __shared__ __align__(16) __half Vs[3][64 * KVS];
    __shared__ __align__(16) __half Ps[64 * PSS];

    int tid = threadIdx.x;
    int w = tid >> 5, lane = tid & 31;
    int lg = lane >> 2, lt = lane & 3;
    int h = blockIdx.y, b = blockIdx.z;
    int qtiles = Lq >> 6;
    int split = blockIdx.x / qtiles;
    int q0 = (blockIdx.x - split * qtiles) * 64;
    int wm = w * 16;
    int ldrow = lane & 15;
    int ldcol = (lane >> 4) * 8;

    int NJ = (Lk >> 6) / nsplit;
    int jbase = split * NJ;

    auto loadTile = [&](__half* dst, const __half* src) {
#pragma unroll
        for (int i = 0; i < 2; i++) {
            int id = tid + 128 * i;
            int row = id >> 2, gr = id & 3;
            cp16(dst + row * KVS + gr * 8, src + (size_t)row * E + gr * 8);
        }
    };
    auto loadKV = [&](int s, int chunk) {
        loadTile(Ks[s], Kt + ((size_t)(b * Lk + (chunk << 6))) * E + h * KD);
        loadTile(Vs[s], V  + ((size_t)(b * Lk + (chunk << 6))) * E + h * KD);
        CP_COMMIT();
    };

    loadTile(Qs, Q + ((size_t)(b * Lq + q0)) * E + h * KD);
    CP_COMMIT();
    loadKV(0, jbase);
    if (NJ > 1) loadKV(1, jbase + 1);
    CP_WAIT(2);
    __syncthreads();

    uint32_t qf[2][4];
#pragma unroll
    for (int ks = 0; ks < 2; ks++)
        LDSM_X4(qf[ks][0], qf[ks][1], qf[ks][2], qf[ks][3],
                saddr(&Qs[(wm + ldrow) * KVS + ks * 16 + ldcol]));

    float ps0 = 0.f, ps1 = 0.f;
    float oacc[4][4] = {};
    const float* mbase = mask ? (mask + ((size_t)h * Lk + q0) * Lk) : nullptr;
    float sl2 = scale * LOG2E;

    for (int jt = 0; jt < NJ; jt++) {
        int j0 = (jbase + jt) << 6;
        if (jt + 1 < NJ) { CP_WAIT(1); } else { CP_WAIT(0); }
        __syncthreads();
        int s = jt % 3;

        float2 mv[8][2];
        if (mbase) {
            int r0 = wm + lg, r1 = wm + 8 + lg;
#pragma unroll
            for (int ni = 0; ni < 8; ni++) {
                int c = j0 + ni * 8 + lt * 2;
                mv[ni][0] = *(const float2*)&mbase[(size_t)r0 * Lk + c];
                mv[ni][1] = *(const float2*)&mbase[(size_t)r1 * Lk + c];
            }
        }

        float sacc[8][4];
#pragma unroll
        for (int ni = 0; ni < 8; ni++)
#pragma unroll
            for (int c = 0; c < 4; c++) sacc[ni][c] = 0.f;
#pragma unroll
        for (int ks = 0; ks < 2; ks++) {
#pragma unroll
            for (int nb = 0; nb < 4; nb++) {
                uint32_t r0, r1, r2, r3;
                LDSM_X4(r0, r1, r2, r3,
                        saddr(&Ks[s][(nb * 16 + ldrow) * KVS + ks * 16 + ldcol]));
                MMA_F16(sacc[2 * nb],     qf[ks][0], qf[ks][1], qf[ks][2], qf[ks][3], r0, r2);
                MMA_F16(sacc[2 * nb + 1], qf[ks][0], qf[ks][1], qf[ks][2], qf[ks][3], r1, r3);
            }
        }

#pragma unroll
        for (int ni = 0; ni < 8; ni++) {
            float p0, p1, p2, p3;
            if (mbase) {
                p0 = exp2f((sacc[ni][0] + mv[ni][0].x) * LOG2E);
                p1 = exp2f((sacc[ni][1] + mv[ni][0].y) * LOG2E);
                p2 = exp2f((sacc[ni][2] + mv[ni][1].x) * LOG2E);
                p3 = exp2f((sacc[ni][3] + mv[ni][1].y) * LOG2E);
            } else {
                p0 = exp2f(sacc[ni][0] * sl2);
                p1 = exp2f(sacc[ni][1] * sl2);
                p2 = exp2f(sacc[ni][2] * sl2);
                p3 = exp2f(sacc[ni][3] * sl2);
            }
            ps0 += p0 + p1;
            ps1 += p2 + p3;
            int c = ni * 8 + lt * 2;
            *(__half2*)&Ps[(wm + lg) * PSS + c]     = __floats2half2_rn(p0, p1);
            *(__half2*)&Ps[(wm + 8 + lg) * PSS + c] = __floats2half2_rn(p2, p3);
        }
        __syncwarp();

#pragma unroll
        for (int ks = 0; ks < 4; ks++) {
            uint32_t pa0, pa1, pa2, pa3;
            LDSM_X4(pa0, pa1, pa2, pa3,
                    saddr(&Ps[(wm + ldrow) * PSS + ks * 16 + ldcol]));
            uint32_t v0, v1, v2, v3;
            LDSM_X4T(v0, v1, v2, v3,
                     saddr(&Vs[s][(ks * 16 + ldrow) * KVS + 0 + ldcol]));
            uint32_t u0, u1, u2, u3;
            LDSM_X4T(u0, u1, u2, u3,
                     saddr(&Vs[s][(ks * 16 + ldrow) * KVS + 16 + ldcol]));
            MMA_F16(oacc[0], pa0, pa1, pa2, pa3, v0, v1);
            MMA_F16(oacc[1], pa0, pa1, pa2, pa3, v2, v3);
            MMA_F16(oacc[2], pa0, pa1, pa2, pa3, u0, u1);
            MMA_F16(oacc[3], pa0, pa1, pa2, pa3, u2, u3);
        }
        if (jt + 2 < NJ) loadKV((jt + 2) % 3, jbase + jt + 2);
    }

    ps0 += __shfl_xor_sync(0xffffffff, ps0, 1);
    ps0 += __shfl_xor_sync(0xffffffff, ps0, 2);
    ps1 += __shfl_xor_sync(0xffffffff, ps1, 1);
    ps1 += __shfl_xor_sync(0xffffffff, ps1, 2);

    int r0 = q0 + wm + lg, r1 = r0 + 8;
    if (nsplit == 1) {
        float inv0 = 1.f / ps0, inv1 = 1.f / ps1;
#pragma unroll
        for (int ni = 0; ni < 4; ni++) {
            int c = h * KD + ni * 8 + lt * 2;
            *(__half2*)&O[((size_t)(b * Lq + r0)) * E + c] =
                __floats2half2_rn(oacc[ni][0] * inv0, oacc[ni][1] * inv0);
            *(__half2*)&O[((size_t)(b * Lq + r1)) * E + c] =
                __floats2half2_rn(oacc[ni][2] * inv1, oacc[ni][3] * inv1);
        }
    } else {
        size_t base = (size_t)split * Bb * Lq;
#pragma unroll
        for (int ni = 0; ni < 4; ni++) {
            int c = h * KD + ni * 8 + lt * 2;
            *(float2*)&PO[(base + b * Lq + r0) * E + c] =
                make_float2(oacc[ni][0], oacc[ni][1]);
            *(float2*)&PO[(base + b * Lq + r1) * E + c] =
                make_float2(oacc[ni][2], oacc[ni][3]);
        }
        if (lt == 0) {
            size_t plb = (((size_t)split * Bb + b) * HEADS + h) * Lq;
            PL[plb + r0] = ps0;
            PL[plb + r1] = ps1;
        }
    }
}

// ---------------- split-KV reduce ----------------------------------------
__global__ void attn_reduce_kernel(const float* __restrict__ PO,
                                   const float* __restrict__ PL,
                                   __half* __restrict__ out) {
    int idx = blockIdx.x * 256 + threadIdx.x;
    int e = idx & (E - 1);
    int bq = idx >> 8;
    int q = bq & (NQ - 1);
    int b = bq >> 6;
    int h = e >> 5;
    float num = 0.f, den = 0.f;
#pragma unroll
    for (int s = 0; s < NSPLIT; s++) {
        num += PO[((size_t)s * Bb * NQ + bq) * E + e];
        den += PL[(((size_t)s * Bb + b) * HEADS + h) * NQ + q];
    }
    out[idx] = __float2half(num / den);
}

// ---------------- launcher ----------------------------------------------
extern "C" void kernel_launch(void* const* d_in, const int* in_sizes, int n_in,
                              void* d_out, int out_size) {
    const float* x       = (const float*)d_in[0];
    const float* queries = (const float*)d_in[1];
    const float* sn      = (const float*)d_in[2];
    const float* cs      = (const float*)d_in[3];
    const float* mask    = (const float*)d_in[4];
    const float* ln1_g   = (const float*)d_in[5];
    const float* ln1_b   = (const float*)d_in[6];
    const float* ln2_g   = (const float*)d_in[7];
    const float* ln2_b   = (const float*)d_in[8];
    const float* wq      = (const float*)d_in[9];
    const float* bq      = (const float*)d_in[10];
    const float* wk      = (const float*)d_in[11];
    const float* bk      = (const float*)d_in[12];
    const float* wv      = (const float*)d_in[13];
    const float* bv      = (const float*)d_in[14];
    const float* lepe_w  = (const float*)d_in[15];
    const float* lepe_b  = (const float*)d_in[16];
    const float* wo      = (const float*)d_in[17];
    const float* bo      = (const float*)d_in[18];
    const float* fc1_w   = (const float*)d_in[19];
    const float* fc1_b   = (const float*)d_in[20];
    const float* fc2_w   = (const float*)d_in[21];
    const float* fc2_b   = (const float*)d_in[22];
    const float* pos_w   = (const float*)d_in[23];
    const float* pos_b   = (const float*)d_in[24];
    const float* ca_in_w = (const float*)d_in[25];
    const float* ca_in_b = (const float*)d_in[26];
    const float* ca_out_w= (const float*)d_in[27];
    const float* ca_out_b= (const float*)d_in[28];

    void* sp = nullptr;
    cudaGetSymbolAddress(&sp, g_scratch);
    float* S = (float*)sp;
    float* X1   = S + OFF_X1;
    float* LEPE = S + OFF_LEPE;
    float* X2   = S + OFF_X2;
    float* Q2   = S + OFF_Q2;
    float* PO   = S + OFF_PO;
    float* PL   = S + OFF_PL;
    __half* HN   = (__half*)(S + OFF_HN);
    __half* QH   = (__half*)(S + OFF_QH);
    __half* KH   = (__half*)(S + OFF_KH);
    __half* VH   = (__half*)(S + OFF_VH);
    __half* AOH  = (__half*)(S + OFF_AOH);
    __half* XH   = (__half*)(S + OFF_XH);
    __half* CKH  = (__half*)(S + OFF_CKH);
    __half* CVH  = (__half*)(S + OFF_CVH);
    __half* FF   = (__half*)(S + OFF_FF);
    __half* CQH  = (__half*)(S + OFF_CQH);
    __half* CAOH = (__half*)(S + OFF_CAOH);
    __half* QLN  = (__half*)(S + OFF_QLN);
    __half* QLN2 = (__half*)(S + OFF_QLN2);
    __half* QFF  = (__half*)(S + OFF_QFF);
    __half* WHb  = (__half*)(S + OFF_WH);

    float* OX = (float*)d_out;
    float* OQ = OX + (size_t)Bb * L * E;

    const int MTOK = Bb * L;   // 8192
    const int MQ   = Bb * NQ;  // 512
    dim3 c5(WW / 4, HH, Bb);

    static cudaStream_t s2 = nullptr, s3 = nullptr;
    static cudaEvent_t ev0 = nullptr, evW = nullptr, evQ = nullptr,
                       evV = nullptr, evL = nullptr;
    if (!s2) {
        cudaStreamCreateWithFlags(&s2, cudaStreamNonBlocking);
        cudaStreamCreateWithFlags(&s3, cudaStreamNonBlocking);
        cudaEventCreateWithFlags(&ev0, cudaEventDisableTiming);
        cudaEventCreateWithFlags(&evW, cudaEventDisableTiming);
        cudaEventCreateWithFlags(&evQ, cudaEventDisableTiming);
        cudaEventCreateWithFlags(&evV, cudaEventDisableTiming);
        cudaEventCreateWithFlags(&evL, cudaEventDisableTiming);
        cudaFuncSetAttribute(gemm_kernel,
            cudaFuncAttributeMaxDynamicSharedMemorySize, GSMB);
        cudaFuncSetAttribute(qkv_gemm_kernel,
            cudaFuncAttributeMaxDynamicSharedMemorySize, GSMB);
        cudaFuncSetAttribute(ckv_gemm_kernel,
            cudaFuncAttributeMaxDynamicSharedMemorySize, GSMB);
    }

    // fork s2: weights + queries prologue
    cudaEventRecord(ev0, 0);
    cudaStreamWaitEvent(s2, ev0, 0);
    wconv_kernel<<<dim3(128, 8), 256, 0, s2>>>(wq, wk, wv, wo, fc1_w, fc2_w,
                                               ca_in_w, ca_out_w, WHb);
    cudaEventRecord(evW, s2);
    ln_kernel<<<MQ / 8, 256, 0, s2>>>(queries, ln1_g, ln1_b, QLN);
    gemm_kernel<<<dim3(E/64, MQ/128), 256, GSMB, s2>>>(
        QLN, WHb + WH_CAIN, ca_in_b, nullptr, nullptr, CQH, MQ, E, E, 1.f, EPI_NONE);
    cudaEventRecord(evQ, s2);

    // main: dwconv3 + LN1 (warp-per-pixel)
    dwconv3_ln_kernel<<<(Bb * HH * WW) / 8, 256>>>(x, pos_w, pos_b, ln1_g, ln1_b, X1, HN);
    cudaStreamWaitEvent(0, evW, 0);
    qkv_gemm_kernel<<<dim3(E/64, MTOK/128, 3), 256, GSMB>>>(
        HN, WHb, bq, bk, bv, QH, KH, VH, sn, cs);
    cudaEventRecord(evV, 0);

    // fork s3: dwconv5 concurrent with self-attention
    cudaStreamWaitEvent(s3, evV, 0);
    dwconv5_kernel<<<c5, 256, 0, s3>>>(VH, lepe_w, lepe_b, LEPE);
    cudaEventRecord(evL, s3);

    attn_f16_kernel<<<dim3(L/64, HEADS, Bb), 128>>>(
        QH, KH, VH, mask, AOH, nullptr, nullptr, L, L, 1.f, 1);
    cudaStreamWaitEvent(0, evL, 0);
    add_lepe_kernel<<<(Bb * L * E) / 1024, 256>>>(AOH, LEPE);

    gemm_kernel<<<dim3(E/64, MTOK/128), 256, GSMB>>>(AOH, WHb + WH_WO, bo, X1, X2, nullptr, MTOK, E, E, 1.f, EPI_NONE);
    ln_kernel<<<MTOK / 8, 256>>>(X2, ln2_g, ln2_b, HN);
    gemm_kernel<<<dim3(FFN/64, MTOK/128), 256, GSMB>>>(HN, WHb + WH_FC1, fc1_b, nullptr, nullptr, FF, MTOK, FFN, E, 1.f, EPI_GELU);
    gemm_kernel<<<dim3(E/64, MTOK/128), 256, GSMB>>>(FF, WHb + WH_FC2, fc2_b, X2, OX, XH, MTOK, E, FFN, 1.f, EPI_NONE);
    ckv_gemm_kernel<<<dim3(E/64, MTOK/128, 2), 256, GSMB>>>(XH, WHb, ca_in_b, CKH, CVH);
    cudaStreamWaitEvent(0, evQ, 0);
    attn_f16_kernel<<<dim3(NSPLIT, HEADS, Bb), 128>>>(
        CQH, CKH, CVH, nullptr, nullptr, PO, PL, NQ, L, SCALING, NSPLIT);
    attn_reduce_kernel<<<(Bb * NQ * E) / 256, 256>>>(PO, PL, CAOH);
    gemm_kernel<<<dim3(E/64, MQ/128), 256, GSMB>>>(CAOH, WHb + WH_CAOUT, ca_out_b, queries, Q2, nullptr, MQ, E, E, 1.f, EPI_NONE);
    ln_kernel<<<MQ / 8, 256>>>(Q2, ln2_g, ln2_b, QLN2);
    gemm_kernel<<<dim3(FFN/64, MQ/128), 256, GSMB>>>(QLN2, WHb + WH_FC1, fc1_b, nullptr, nullptr, QFF, MQ, FFN, E, 1.f, EPI_GELU);
    gemm_kernel<<<dim3(E/64, MQ/128), 256, GSMB>>>(QFF, WHb + WH_FC2, fc2_b, Q2, OQ, nullptr, MQ, E, FFN, 1.f, EPI_NONE);
}